// round 14
// baseline (speedup 1.0000x reference)
#include <cuda_runtime.h>
#include <cuda_bf16.h>
#include <math.h>
#include <stdint.h>

#define NN 100000
#define EE 1600000
#define CC 128
#define NTILES ((NN + 127) / 128)       // 782
#define PGRID 148
#define GTHREADS 512
#define SCAN_BLOCKS ((NN + 255) / 256)  // 391

// ---------------------------------------------------------------------------
// Scratch (allocation-free rule: __device__ globals)
// ---------------------------------------------------------------------------
__device__ float g_h[(size_t)NN * CC];     // fp32 h (gather source + resid + LN)
__device__ float g_tmp[(size_t)NN * CC];   // fp32 h@Wsg + bsg

__device__ __nv_bfloat16 g_uh[(size_t)NN * CC],  g_ul[(size_t)NN * CC];   // lift-hidden / u
__device__ __nv_bfloat16 g_hh[(size_t)NN * CC],  g_hl[(size_t)NN * CC];   // h split
__device__ __nv_bfloat16 g_agh[(size_t)NN * CC], g_agl[(size_t)NN * CC];  // gathered h

__device__ float g_sev[NN];                // per-row sum of edge values
__device__ float g_wnb[2 * 16384];         // Wn @ W1b (fp32)
__device__ float g_wsg[2 * 16384];         // Ws @ W1a (fp32)
__device__ float g_bnb[2 * CC];            // bn @ W1b
__device__ float g_bsg[2 * CC];            // bs @ W1a + bg1
__device__ float g_zero[CC];               // zero bias

// CSR scratch
__device__ int   g_cnt[NN];
__device__ int   g_rowstart[NN + 1];
__device__ int   g_cursor[NN];
__device__ int   g_bsum[SCAN_BLOCKS];
__device__ int   g_boff[SCAN_BLOCKS];
__device__ int   g_ecol[EE];
__device__ float g_eval[EE];

// Pre-converted bf16 weight tiles (hi/lo split), layout [slot][n][k]
// slots: [0]=lift2; per layer l: [1+3l]=Wsg, [2+3l]=Wnb, [3+3l]=gate2.
#define WSLOTS 7
__device__ __nv_bfloat16 g_wbh[(size_t)WSLOTS * 16384];
__device__ __nv_bfloat16 g_wbl[(size_t)WSLOTS * 16384];

__device__ __forceinline__ float gelu_f(float v) {
    return 0.5f * v * (1.0f + erff(v * 0.7071067811865475f));
}
__device__ __forceinline__ void split_bf16(float v, __nv_bfloat16& hi, __nv_bfloat16& lo) {
    hi = __float2bfloat16(v);
    lo = __float2bfloat16(v - __bfloat162float(hi));
}

// ---------------------------------------------------------------------------
// mma.sync / cp.async helpers
// ---------------------------------------------------------------------------
__device__ __forceinline__ void ldsm_x4(uint32_t* r, uint32_t addr) {
    asm volatile("ldmatrix.sync.aligned.m8n8.x4.shared.b16 {%0,%1,%2,%3}, [%4];"
                 : "=r"(r[0]), "=r"(r[1]), "=r"(r[2]), "=r"(r[3]) : "r"(addr));
}
__device__ __forceinline__ void mma16816(float* d, const uint32_t* a, const uint32_t* b) {
    asm volatile(
        "mma.sync.aligned.m16n8k16.row.col.f32.bf16.bf16.f32 "
        "{%0,%1,%2,%3}, {%4,%5,%6,%7}, {%8,%9}, {%0,%1,%2,%3};"
        : "+f"(d[0]), "+f"(d[1]), "+f"(d[2]), "+f"(d[3])
        : "r"(a[0]), "r"(a[1]), "r"(a[2]), "r"(a[3]), "r"(b[0]), "r"(b[1]));
}
__device__ __forceinline__ void cp16(uint32_t dst, const void* src, int srcsize) {
    asm volatile("cp.async.cg.shared.global [%0], [%1], 16, %2;"
                 :: "r"(dst), "l"(src), "r"(srcsize) : "memory");
}
__device__ __forceinline__ void cp_commit() {
    asm volatile("cp.async.commit_group;" ::: "memory");
}
__device__ __forceinline__ void cp_wait_all() {
    asm volatile("cp.async.wait_group 0;" ::: "memory");
}

// ---------------------------------------------------------------------------
// Smem layout (6 tiles of 34816B)
// ---------------------------------------------------------------------------
#define ROWB 272
#define TILEB (128 * ROWB)          // 34816
#define SM_AH 0
#define SM_AL TILEB
#define SM_B0 (2 * TILEB)
#define SM_B1 (4 * TILEB)
#define SM_TOTAL (6 * TILEB)        // 208896

// 16-warp MMA over one staged 128-K tile: warp tile = 16 rows x 64 cols.
__device__ __forceinline__ void mma_chunk16(float acc[8][4], uint32_t aH,
                                            uint32_t aL, uint32_t bH, uint32_t bL) {
#pragma unroll
    for (int ks = 0; ks < 8; ks++) {
        uint32_t ah[4], al[4], bh[4][4], bl[4][4];
        ldsm_x4(ah, aH + ks * 32);
        ldsm_x4(al, aL + ks * 32);
#pragma unroll
        for (int np = 0; np < 4; np++) {
            ldsm_x4(bh[np], bH + ks * 32 + np * 16 * ROWB);
            ldsm_x4(bl[np], bL + ks * 32 + np * 16 * ROWB);
        }
#pragma unroll
        for (int nt = 0; nt < 8; nt++) {
            uint32_t bbh[2] = { bh[nt >> 1][(nt & 1) * 2], bh[nt >> 1][(nt & 1) * 2 + 1] };
            uint32_t bbl[2] = { bl[nt >> 1][(nt & 1) * 2], bl[nt >> 1][(nt & 1) * 2 + 1] };
            mma16816(acc[nt], ah, bbh);
            mma16816(acc[nt], ah, bbl);
            mma16816(acc[nt], al, bbh);
        }
    }
}

#define ACC_ZERO16(acc)                                 \
    _Pragma("unroll")                                   \
    for (int nt = 0; nt < 8; nt++)                      \
        _Pragma("unroll")                               \
        for (int e = 0; e < 4; e++) acc[nt][e] = 0.0f;

__device__ __forceinline__ void stage_A_split(uint32_t abase,
                                              const __nv_bfloat16* __restrict__ Ah,
                                              const __nv_bfloat16* __restrict__ Al,
                                              int m0, int tid) {
#pragma unroll
    for (int i = 0; i < 4; i++) {
        int ci = tid + i * GTHREADS;
        int row = ci >> 4, ch = ci & 15;
        int gm = m0 + row;
        int ss = (gm < NN) ? 16 : 0;
        int gms = (gm < NN) ? gm : (NN - 1);
        uint32_t off = (uint32_t)(row * ROWB + ch * 16);
        cp16(abase + off, Ah + (size_t)gms * 128 + ch * 8, ss);
        cp16(abase + TILEB + off, Al + (size_t)gms * 128 + ch * 8, ss);
    }
}
__device__ __forceinline__ void stage_B(uint32_t bbase, const __nv_bfloat16* __restrict__ Bh,
                                        const __nv_bfloat16* __restrict__ Bl, int tid) {
#pragma unroll
    for (int i = 0; i < 4; i++) {
        int ci = tid + i * GTHREADS;
        int row = ci >> 4, ch = ci & 15;
        uint32_t off = (uint32_t)(row * ROWB + ch * 16);
        cp16(bbase + off, Bh + ci * 8, 16);
        cp16(bbase + TILEB + off, Bl + ci * 8, 16);
    }
}

// ---------------------------------------------------------------------------
// Persistent GEMM, 512 threads. RESID: 0 none, 1 post-act, 2 pre-act.
// SCV: add sev[r]*cvec[col] pre-activation. WF32/WSPLIT select outputs.
// ---------------------------------------------------------------------------
template <int GELU, int RESID, int WF32, int WSPLIT, int SCV>
__global__ void __launch_bounds__(GTHREADS, 1) gemm_pers(
    const __nv_bfloat16* __restrict__ Ah, const __nv_bfloat16* __restrict__ Al,
    const __nv_bfloat16* __restrict__ Bh, const __nv_bfloat16* __restrict__ Bl,
    const float* __restrict__ bias, const float* __restrict__ R,
    const float* __restrict__ sev, const float* __restrict__ cvec,
    float* __restrict__ OutF, __nv_bfloat16* __restrict__ OutH,
    __nv_bfloat16* __restrict__ OutL) {
    extern __shared__ __align__(16) char smem[];
    const uint32_t sb = (uint32_t)__cvta_generic_to_shared(smem);
    const int tid = threadIdx.x;
    const int lane = tid & 31;
    const int warp_m = (tid >> 5) >> 1;   // 0..7, 16 rows
    const int warp_n = (tid >> 5) & 1;    // 0..1, 64 cols

    const uint32_t a_lane = (uint32_t)((lane & 15) * ROWB + (lane >> 4) * 16) +
                            (uint32_t)(warp_m * 16 * ROWB);
    const uint32_t b_lane = (uint32_t)(((lane & 7) + ((lane >> 4) & 1) * 8) * ROWB +
                                       ((lane >> 3) & 1) * 16) +
                            (uint32_t)(warp_n * 64 * ROWB);
    const uint32_t bH = sb + SM_B0 + b_lane;
    const uint32_t bL = sb + SM_B0 + TILEB + b_lane;

    float b0[8], b1[8], cv0[8], cv1[8];
#pragma unroll
    for (int nt = 0; nt < 8; nt++) {
        int col = warp_n * 64 + nt * 8 + (lane & 3) * 2;
        b0[nt] = __ldg(bias + col);
        b1[nt] = __ldg(bias + col + 1);
        if (SCV) {
            cv0[nt] = __ldg(cvec + col);
            cv1[nt] = __ldg(cvec + col + 1);
        }
    }

    stage_B(sb + SM_B0, Bh, Bl, tid);
    int tile = blockIdx.x;
    if (tile < NTILES) stage_A_split(sb + SM_AH, Ah, Al, tile * 128, tid);
    cp_commit();
    cp_wait_all();
    __syncthreads();

    int buf = 0;
    for (; tile < NTILES; tile += PGRID) {
        const int m0 = tile * 128;
        const int nxt = tile + PGRID;
        if (nxt < NTILES)
            stage_A_split(sb + (buf ? SM_AH : SM_B1), Ah, Al, nxt * 128, tid);
        cp_commit();

        float acc[8][4];
        ACC_ZERO16(acc);
        const uint32_t aB = sb + (buf ? SM_B1 : SM_AH);
        mma_chunk16(acc, aB + a_lane, aB + TILEB + a_lane, bH, bL);

        int r0 = m0 + warp_m * 16 + (lane >> 2);
#pragma unroll
        for (int half = 0; half < 2; half++) {
            int r = r0 + half * 8;
            if (r >= NN) continue;
            const float* rrow = RESID ? (R + (size_t)r * 128) : nullptr;
            float sv = SCV ? __ldg(sev + r) : 0.0f;
#pragma unroll
            for (int nt = 0; nt < 8; nt++) {
                int col = warp_n * 64 + nt * 8 + (lane & 3) * 2;
                float x0 = acc[nt][half * 2 + 0] + b0[nt];
                float x1 = acc[nt][half * 2 + 1] + b1[nt];
                if (SCV) { x0 = fmaf(sv, cv0[nt], x0); x1 = fmaf(sv, cv1[nt], x1); }
                float2 rr;
                if (RESID) rr = *(const float2*)(rrow + col);
                if (RESID == 2) { x0 += rr.x; x1 += rr.y; }
                if (GELU) { x0 = gelu_f(x0); x1 = gelu_f(x1); }
                if (RESID == 1) { x0 += rr.x; x1 += rr.y; }
                if (WF32)
                    *(float2*)(OutF + (size_t)r * 128 + col) = make_float2(x0, x1);
                if (WSPLIT) {
                    __nv_bfloat16 h0, l0, h1, l1;
                    split_bf16(x0, h0, l0);
                    split_bf16(x1, h1, l1);
                    *(__nv_bfloat162*)(OutH + (size_t)r * 128 + col) =
                        __nv_bfloat162(h0, h1);
                    *(__nv_bfloat162*)(OutL + (size_t)r * 128 + col) =
                        __nv_bfloat162(l0, l1);
                }
            }
        }
        cp_wait_all();
        __syncthreads();
        buf ^= 1;
    }
}

// ---------------------------------------------------------------------------
// Combined weights (fp32, exact)
// ---------------------------------------------------------------------------
__global__ void k_wcomb(const float* __restrict__ nw, const float* __restrict__ sw,
                        const float* __restrict__ gw1) {
    int idx = blockIdx.x * blockDim.x + threadIdx.x;
    if (idx >= 4 * 16384) return;
    int which = idx >> 15;            // 0 = Wnb, 1 = Wsg
    int sub = idx & 32767;
    int l = sub >> 14;
    int k = (sub >> 7) & 127;
    int n = sub & 127;
    const float* a;
    const float* b;
    if (which == 0) {
        a = nw + (size_t)l * 16384 + k * 128;
        b = gw1 + (size_t)l * 32768 + 16384 + n;
    } else {
        a = sw + (size_t)l * 16384 + k * 128;
        b = gw1 + (size_t)l * 32768 + n;
    }
    float s = 0.0f;
#pragma unroll 8
    for (int m = 0; m < 128; m++) s = fmaf(a[m], b[(size_t)m * 128], s);
    if (which == 0) g_wnb[sub] = s;
    else            g_wsg[sub] = s;
}
__global__ void k_bcomb(const float* __restrict__ nbw, const float* __restrict__ sb,
                        const float* __restrict__ gb1, const float* __restrict__ gw1) {
    int idx = blockIdx.x * blockDim.x + threadIdx.x;
    if (idx >= 4 * CC) return;
    int which = idx >> 8;             // 0 = bnb, 1 = bsg
    int l = (idx >> 7) & 1, n = idx & 127;
    float s = 0.0f;
    if (which == 0) {
#pragma unroll 8
        for (int m = 0; m < 128; m++)
            s = fmaf(nbw[l * 128 + m],
                     gw1[(size_t)l * 32768 + 16384 + (size_t)m * 128 + n], s);
        g_bnb[l * CC + n] = s;
    } else {
#pragma unroll 8
        for (int m = 0; m < 128; m++)
            s = fmaf(sb[l * 128 + m], gw1[(size_t)l * 32768 + (size_t)m * 128 + n], s);
        g_bsg[l * CC + n] = s + gb1[l * 128 + n];
    }
}

// ---------------------------------------------------------------------------
// Weight conversion: fp32 W[K,N] -> bf16 hi/lo B[N,K]
// ---------------------------------------------------------------------------
__global__ void wconv_kernel(const float* __restrict__ lw2,
                             const float* __restrict__ gw2) {
    int idx = blockIdx.x * blockDim.x + threadIdx.x;
    if (idx >= WSLOTS * 16384) return;
    int slot = idx >> 14;
    int within = idx & 16383;
    int n = within >> 7;
    int k = within & 127;
    const float* src;
    if (slot == 0) {
        src = lw2 + k * 128 + n;
    } else {
        int l = (slot - 1) / 3, j = (slot - 1) % 3;
        if (j == 0)      src = g_wsg + (size_t)l * 16384 + k * 128 + n;
        else if (j == 1) src = g_wnb + (size_t)l * 16384 + k * 128 + n;
        else             src = gw2 + (size_t)l * 16384 + k * 128 + n;
    }
    __nv_bfloat16 hi, lo;
    split_bf16(*src, hi, lo);
    g_wbh[idx] = hi;
    g_wbl[idx] = lo;
}

// ---------------------------------------------------------------------------
// CSR build
// ---------------------------------------------------------------------------
__global__ void k_zero_cnt() {
    int i = blockIdx.x * blockDim.x + threadIdx.x;
    if (i < NN) g_cnt[i] = 0;
}
__global__ void k_count(const int* __restrict__ ei) {
    int e = blockIdx.x * blockDim.x + threadIdx.x;
    if (e < EE) atomicAdd(&g_cnt[ei[e]], 1);
}
__global__ void k_blocksum() {
    __shared__ int sh[256];
    int i = blockIdx.x * 256 + threadIdx.x;
    int v = (i < NN) ? g_cnt[i] : 0;
    sh[threadIdx.x] = v;
    __syncthreads();
    for (int s = 128; s; s >>= 1) {
        if (threadIdx.x < s) sh[threadIdx.x] += sh[threadIdx.x + s];
        __syncthreads();
    }
    if (threadIdx.x == 0) g_bsum[blockIdx.x] = sh[0];
}
__global__ void k_scan_bsum() {
    __shared__ int sh[512];
    int t = threadIdx.x;
    sh[t] = (t < SCAN_BLOCKS) ? g_bsum[t] : 0;
    __syncthreads();
    for (int off = 1; off < 512; off <<= 1) {
        int v = (t >= off) ? sh[t - off] : 0;
        __syncthreads();
        sh[t] += v;
        __syncthreads();
    }
    if (t < SCAN_BLOCKS) g_boff[t] = sh[t] - g_bsum[t];
}
__global__ void k_rowstart() {
    __shared__ int sh[256];
    int i = blockIdx.x * 256 + threadIdx.x;
    int v = (i < NN) ? g_cnt[i] : 0;
    sh[threadIdx.x] = v;
    __syncthreads();
    for (int off = 1; off < 256; off <<= 1) {
        int u = (threadIdx.x >= off) ? sh[threadIdx.x - off] : 0;
        __syncthreads();
        sh[threadIdx.x] += u;
        __syncthreads();
    }
    if (i < NN) {
        int excl = sh[threadIdx.x] - v + g_boff[blockIdx.x];
        g_rowstart[i] = excl;
        g_cursor[i] = excl;
        if (i == NN - 1) g_rowstart[NN] = excl + v;
    }
}
__global__ void k_fill(const int* __restrict__ ei, const float* __restrict__ ev) {
    int e = blockIdx.x * blockDim.x + threadIdx.x;
    if (e >= EE) return;
    int row = ei[e];
    int pos = atomicAdd(&g_cursor[row], 1);
    g_ecol[pos] = ei[EE + e];
    g_eval[pos] = ev[e];
}

// ---------------------------------------------------------------------------
// Pull aggregation of h: gh[r] = sum ev*h[col] (split); sev[r] = sum ev.
// ---------------------------------------------------------------------------
__global__ void k_aggr() {
    int r = blockIdx.x * 8 + (threadIdx.x >> 5);
    if (r >= NN) return;
    int lane = threadIdx.x & 31;
    int s = g_rowstart[r];
    int e = g_rowstart[r + 1];
    float acc[4] = {0.f, 0.f, 0.f, 0.f};
    float sev = 0.f;
    for (int j = s; j < e; j++) {
        int c = __ldg(&g_ecol[j]);
        float v = __ldg(&g_eval[j]);
        sev += v;
        const float* srow = g_h + (size_t)c * CC + lane;
        acc[0] = fmaf(__ldg(srow),      v, acc[0]);
        acc[1] = fmaf(__ldg(srow + 32), v, acc[1]);
        acc[2] = fmaf(__ldg(srow + 64), v, acc[2]);
        acc[3] = fmaf(__ldg(srow + 96), v, acc[3]);
    }
#pragma unroll
    for (int i = 0; i < 4; i++) {
        __nv_bfloat16 hi, lo;
        split_bf16(acc[i], hi, lo);
        g_agh[(size_t)r * CC + lane + i * 32] = hi;
        g_agl[(size_t)r * CC + lane + i * 32] = lo;
    }
    if (lane == 0) g_sev[r] = sev;
}

// ---------------------------------------------------------------------------
// Lift stage 1 + LayerNorm
// ---------------------------------------------------------------------------
__global__ void lift_hidden_kernel(const float* __restrict__ x,
                                   const float* __restrict__ w1,
                                   const float* __restrict__ b1) {
    int idx = blockIdx.x * blockDim.x + threadIdx.x;
    if (idx >= NN * CC) return;
    int n = idx >> 7;
    int c = idx & 127;
    const float* xr = x + (size_t)n * 9 + 3;
    float acc = b1[c];
#pragma unroll
    for (int i = 0; i < 6; i++)
        acc = fmaf(xr[i], w1[i * CC + c], acc);
    float v = gelu_f(acc);
    __nv_bfloat16 hi, lo;
    split_bf16(v, hi, lo);
    g_uh[idx] = hi;
    g_ul[idx] = lo;
}

__global__ void ln_kernel(const float* __restrict__ h,
                          const float* __restrict__ g,
                          const float* __restrict__ b,
                          float* __restrict__ out) {
    int n = blockIdx.x * 8 + (threadIdx.x >> 5);
    if (n >= NN) return;
    int lane = threadIdx.x & 31;
    const float* r = h + (size_t)n * CC;
    float v[4];
    float s = 0.f;
#pragma unroll
    for (int i = 0; i < 4; i++) { v[i] = r[lane + i * 32]; s += v[i]; }
#pragma unroll
    for (int o = 16; o; o >>= 1) s += __shfl_xor_sync(0xffffffffu, s, o);
    float mu = s * (1.f / 128.f);
    float q = 0.f;
#pragma unroll
    for (int i = 0; i < 4; i++) { float d = v[i] - mu; q = fmaf(d, d, q); }
#pragma unroll
    for (int o = 16; o; o >>= 1) q += __shfl_xor_sync(0xffffffffu, q, o);
    float inv = rsqrtf(q * (1.f / 128.f) + 1e-5f);
#pragma unroll
    for (int i = 0; i < 4; i++) {
        int c = lane + i * 32;
        out[(size_t)n * CC + c] = fmaf((v[i] - mu) * inv, g[c], b[c]);
    }
}

// ---------------------------------------------------------------------------
extern "C" void kernel_launch(void* const* d_in, const int* in_sizes, int n_in,
                              void* d_out, int out_size) {
    const float* x   = (const float*)d_in[0];
    const int*   ei  = (const int*)d_in[1];
    const float* ev  = (const float*)d_in[2];
    const float* lw1 = (const float*)d_in[3];
    const float* lb1 = (const float*)d_in[4];
    const float* lw2 = (const float*)d_in[5];
    const float* lb2 = (const float*)d_in[6];
    const float* sw  = (const float*)d_in[7];
    const float* sb  = (const float*)d_in[8];
    const float* nw  = (const float*)d_in[9];
    const float* nbw = (const float*)d_in[10];
    const float* gw1 = (const float*)d_in[11];
    const float* gb1 = (const float*)d_in[12];
    const float* gw2 = (const float*)d_in[13];
    const float* gb2 = (const float*)d_in[14];
    const float* ng  = (const float*)d_in[15];
    const float* nbt = (const float*)d_in[16];
    float* out = (float*)d_out;

    float *h, *tmp, *sev, *bnb, *bsg, *zero;
    cudaGetSymbolAddress((void**)&h, g_h);
    cudaGetSymbolAddress((void**)&tmp, g_tmp);
    cudaGetSymbolAddress((void**)&sev, g_sev);
    cudaGetSymbolAddress((void**)&bnb, g_bnb);
    cudaGetSymbolAddress((void**)&bsg, g_bsg);
    cudaGetSymbolAddress((void**)&zero, g_zero);
    __nv_bfloat16 *wbh, *wbl, *uh, *ul, *hh, *hl, *agh, *agl;
    cudaGetSymbolAddress((void**)&wbh, g_wbh);
    cudaGetSymbolAddress((void**)&wbl, g_wbl);
    cudaGetSymbolAddress((void**)&uh, g_uh);
    cudaGetSymbolAddress((void**)&ul, g_ul);
    cudaGetSymbolAddress((void**)&hh, g_hh);
    cudaGetSymbolAddress((void**)&hl, g_hl);
    cudaGetSymbolAddress((void**)&agh, g_agh);
    cudaGetSymbolAddress((void**)&agl, g_agl);

    cudaFuncSetAttribute(gemm_pers<0, 0, 1, 1, 0>, cudaFuncAttributeMaxDynamicSharedMemorySize, SM_TOTAL);
    cudaFuncSetAttribute(gemm_pers<0, 0, 1, 0, 0>, cudaFuncAttributeMaxDynamicSharedMemorySize, SM_TOTAL);
    cudaFuncSetAttribute(gemm_pers<1, 2, 0, 1, 1>, cudaFuncAttributeMaxDynamicSharedMemorySize, SM_TOTAL);
    cudaFuncSetAttribute(gemm_pers<0, 1, 1, 1, 0>, cudaFuncAttributeMaxDynamicSharedMemorySize, SM_TOTAL);

    // Fork/join resources (created per call; capture-legal, not device allocs)
    cudaStream_t s2;
    cudaStreamCreateWithFlags(&s2, cudaStreamNonBlocking);
    cudaEvent_t evF, evJ, evH[2], evT[2];
    cudaEventCreateWithFlags(&evF, cudaEventDisableTiming);
    cudaEventCreateWithFlags(&evJ, cudaEventDisableTiming);
    for (int l = 0; l < 2; l++) {
        cudaEventCreateWithFlags(&evH[l], cudaEventDisableTiming);
        cudaEventCreateWithFlags(&evT[l], cudaEventDisableTiming);
    }

    // ---- Fork: CSR build on s2, weight prep + lift on main ----
    cudaEventRecord(evF, 0);
    cudaStreamWaitEvent(s2, evF, 0);

    k_zero_cnt<<<SCAN_BLOCKS, 256, 0, s2>>>();
    k_count<<<(EE + 255) / 256, 256, 0, s2>>>(ei);
    k_blocksum<<<SCAN_BLOCKS, 256, 0, s2>>>();
    k_scan_bsum<<<1, 512, 0, s2>>>();
    k_rowstart<<<SCAN_BLOCKS, 256, 0, s2>>>();
    k_fill<<<(EE + 255) / 256, 256, 0, s2>>>(ei, ev);
    cudaEventRecord(evJ, s2);

    k_wcomb<<<(4 * 16384 + 255) / 256, 256>>>(nw, sw, gw1);
    k_bcomb<<<2, 256>>>(nbw, sb, gb1, gw1);
    wconv_kernel<<<(WSLOTS * 16384 + 255) / 256, 256>>>(lw2, gw2);
    lift_hidden_kernel<<<(NN * CC + 255) / 256, 256>>>(x, lw1, lb1);
    gemm_pers<0, 0, 1, 1, 0><<<PGRID, GTHREADS, SM_TOTAL>>>(
        uh, ul, wbh, wbl, lb2, nullptr, nullptr, nullptr, h, hh, hl);

    cudaStreamWaitEvent(0, evJ, 0);   // join: CSR ready

    for (int l = 0; l < 2; l++) {
        const __nv_bfloat16* wsgh = wbh + (size_t)(1 + 3 * l) * 16384;
        const __nv_bfloat16* wsgl = wbl + (size_t)(1 + 3 * l) * 16384;
        const __nv_bfloat16* wnbh = wbh + (size_t)(2 + 3 * l) * 16384;
        const __nv_bfloat16* wnbl = wbl + (size_t)(2 + 3 * l) * 16384;
        const __nv_bfloat16* g2h  = wbh + (size_t)(3 + 3 * l) * 16384;
        const __nv_bfloat16* g2l  = wbl + (size_t)(3 + 3 * l) * 16384;

        // Fork: tmp = h @ Wsg + bsg on s2, k_aggr on main (both need only h)
        cudaEventRecord(evH[l], 0);
        cudaStreamWaitEvent(s2, evH[l], 0);
        gemm_pers<0, 0, 1, 0, 0><<<PGRID, GTHREADS, SM_TOTAL, s2>>>(
            hh, hl, wsgh, wsgl, bsg + l * CC, nullptr, nullptr, nullptr,
            tmp, nullptr, nullptr);
        cudaEventRecord(evT[l], s2);

        k_aggr<<<(NN + 7) / 8, 256>>>();

        cudaStreamWaitEvent(0, evT[l], 0);   // join: tmp ready

        // u = gelu(gh@Wnb + tmp + sev*bnb)  (split out)
        gemm_pers<1, 2, 0, 1, 1><<<PGRID, GTHREADS, SM_TOTAL>>>(
            agh, agl, wnbh, wnbl, zero, tmp, sev, bnb + l * CC,
            nullptr, uh, ul);
        // h = h + u @ Wg2 + bg2  (fp32 + split)
        gemm_pers<0, 1, 1, 1, 0><<<PGRID, GTHREADS, SM_TOTAL>>>(
            uh, ul, g2h, g2l, gb2 + l * CC, h, nullptr, nullptr, h, hh, hl);
    }

    ln_kernel<<<(NN + 7) / 8, 256>>>(h, ng, nbt, out);
}

// round 15
// speedup vs baseline: 1.0351x; 1.0351x over previous
#include <cuda_runtime.h>
#include <cuda_bf16.h>
#include <math.h>
#include <stdint.h>

#define NN 100000
#define EE 1600000
#define CC 128
#define NTILES ((NN + 127) / 128)       // 782
#define PGRID 148
#define GTHREADS 512
#define SCAN_BLOCKS ((NN + 255) / 256)  // 391

// ---------------------------------------------------------------------------
// Scratch (allocation-free rule: __device__ globals)
// ---------------------------------------------------------------------------
__device__ float g_h[(size_t)NN * CC];     // fp32 h (gather source + resid + LN)

__device__ __nv_bfloat16 g_uh[(size_t)NN * CC],  g_ul[(size_t)NN * CC];   // lift-hidden / u
__device__ __nv_bfloat16 g_hh[(size_t)NN * CC],  g_hl[(size_t)NN * CC];   // h split
__device__ __nv_bfloat16 g_agh[(size_t)NN * CC], g_agl[(size_t)NN * CC];  // gathered h

__device__ float g_sev[NN];                // per-row sum of edge values
__device__ float g_wnb[2 * 16384];         // Wn @ W1b (fp32)
__device__ float g_wsg[2 * 16384];         // Ws @ W1a (fp32)
__device__ float g_bnb[2 * CC];            // bn @ W1b
__device__ float g_bsg[2 * CC];            // bs @ W1a + bg1

// CSR scratch
__device__ int   g_cnt[NN];
__device__ int   g_rowstart[NN + 1];
__device__ int   g_cursor[NN];
__device__ int   g_bsum[SCAN_BLOCKS];
__device__ int   g_boff[SCAN_BLOCKS];
__device__ int   g_ecol[EE];
__device__ float g_eval[EE];

// Pre-converted bf16 weight tiles (hi/lo split), layout [slot][n][k]
// slots: [0]=lift2; per layer l: [1+3l]=Wsg, [2+3l]=Wnb, [3+3l]=gate2.
#define WSLOTS 7
__device__ __nv_bfloat16 g_wbh[(size_t)WSLOTS * 16384];
__device__ __nv_bfloat16 g_wbl[(size_t)WSLOTS * 16384];

__device__ __forceinline__ float gelu_f(float v) {
    return 0.5f * v * (1.0f + erff(v * 0.7071067811865475f));
}
__device__ __forceinline__ void split_bf16(float v, __nv_bfloat16& hi, __nv_bfloat16& lo) {
    hi = __float2bfloat16(v);
    lo = __float2bfloat16(v - __bfloat162float(hi));
}

// ---------------------------------------------------------------------------
// mma.sync / cp.async helpers
// ---------------------------------------------------------------------------
__device__ __forceinline__ void ldsm_x4(uint32_t* r, uint32_t addr) {
    asm volatile("ldmatrix.sync.aligned.m8n8.x4.shared.b16 {%0,%1,%2,%3}, [%4];"
                 : "=r"(r[0]), "=r"(r[1]), "=r"(r[2]), "=r"(r[3]) : "r"(addr));
}
__device__ __forceinline__ void mma16816(float* d, const uint32_t* a, const uint32_t* b) {
    asm volatile(
        "mma.sync.aligned.m16n8k16.row.col.f32.bf16.bf16.f32 "
        "{%0,%1,%2,%3}, {%4,%5,%6,%7}, {%8,%9}, {%0,%1,%2,%3};"
        : "+f"(d[0]), "+f"(d[1]), "+f"(d[2]), "+f"(d[3])
        : "r"(a[0]), "r"(a[1]), "r"(a[2]), "r"(a[3]), "r"(b[0]), "r"(b[1]));
}
__device__ __forceinline__ void cp16(uint32_t dst, const void* src, int srcsize) {
    asm volatile("cp.async.cg.shared.global [%0], [%1], 16, %2;"
                 :: "r"(dst), "l"(src), "r"(srcsize) : "memory");
}
__device__ __forceinline__ void cp_commit() {
    asm volatile("cp.async.commit_group;" ::: "memory");
}
__device__ __forceinline__ void cp_wait_all() {
    asm volatile("cp.async.wait_group 0;" ::: "memory");
}

// ---------------------------------------------------------------------------
// Smem layout (6 tiles of 34816B)
// ---------------------------------------------------------------------------
#define ROWB 272
#define TILEB (128 * ROWB)          // 34816
#define SM_AH 0
#define SM_AL TILEB
#define SM_B0 (2 * TILEB)
#define SM_B1 (4 * TILEB)
#define SM_TOTAL (6 * TILEB)        // 208896

// 16-warp MMA over one staged 128-K tile: warp tile = 16 rows x 64 cols.
__device__ __forceinline__ void mma_chunk16(float acc[8][4], uint32_t aH,
                                            uint32_t aL, uint32_t bH, uint32_t bL) {
#pragma unroll
    for (int ks = 0; ks < 8; ks++) {
        uint32_t ah[4], al[4], bh[4][4], bl[4][4];
        ldsm_x4(ah, aH + ks * 32);
        ldsm_x4(al, aL + ks * 32);
#pragma unroll
        for (int np = 0; np < 4; np++) {
            ldsm_x4(bh[np], bH + ks * 32 + np * 16 * ROWB);
            ldsm_x4(bl[np], bL + ks * 32 + np * 16 * ROWB);
        }
#pragma unroll
        for (int nt = 0; nt < 8; nt++) {
            uint32_t bbh[2] = { bh[nt >> 1][(nt & 1) * 2], bh[nt >> 1][(nt & 1) * 2 + 1] };
            uint32_t bbl[2] = { bl[nt >> 1][(nt & 1) * 2], bl[nt >> 1][(nt & 1) * 2 + 1] };
            mma16816(acc[nt], ah, bbh);
            mma16816(acc[nt], ah, bbl);
            mma16816(acc[nt], al, bbh);
        }
    }
}

#define ACC_ZERO16(acc)                                 \
    _Pragma("unroll")                                   \
    for (int nt = 0; nt < 8; nt++)                      \
        _Pragma("unroll")                               \
        for (int e = 0; e < 4; e++) acc[nt][e] = 0.0f;

__device__ __forceinline__ void stage_A_split(uint32_t abase,
                                              const __nv_bfloat16* __restrict__ Ah,
                                              const __nv_bfloat16* __restrict__ Al,
                                              int m0, int tid) {
#pragma unroll
    for (int i = 0; i < 4; i++) {
        int ci = tid + i * GTHREADS;
        int row = ci >> 4, ch = ci & 15;
        int gm = m0 + row;
        int ss = (gm < NN) ? 16 : 0;
        int gms = (gm < NN) ? gm : (NN - 1);
        uint32_t off = (uint32_t)(row * ROWB + ch * 16);
        cp16(abase + off, Ah + (size_t)gms * 128 + ch * 8, ss);
        cp16(abase + TILEB + off, Al + (size_t)gms * 128 + ch * 8, ss);
    }
}
__device__ __forceinline__ void stage_B(uint32_t bbase, const __nv_bfloat16* __restrict__ Bh,
                                        const __nv_bfloat16* __restrict__ Bl, int tid) {
#pragma unroll
    for (int i = 0; i < 4; i++) {
        int ci = tid + i * GTHREADS;
        int row = ci >> 4, ch = ci & 15;
        uint32_t off = (uint32_t)(row * ROWB + ch * 16);
        cp16(bbase + off, Bh + ci * 8, 16);
        cp16(bbase + TILEB + off, Bl + ci * 8, 16);
    }
}

// ---------------------------------------------------------------------------
// Persistent GEMM, 512 threads. RESID: 0 none, 1 post-act. Writes fp32 + split.
// ---------------------------------------------------------------------------
template <int RESID>
__global__ void __launch_bounds__(GTHREADS, 1) gemm_pers(
    const __nv_bfloat16* __restrict__ Ah, const __nv_bfloat16* __restrict__ Al,
    const __nv_bfloat16* __restrict__ Bh, const __nv_bfloat16* __restrict__ Bl,
    const float* __restrict__ bias, const float* __restrict__ R,
    float* __restrict__ OutF, __nv_bfloat16* __restrict__ OutH,
    __nv_bfloat16* __restrict__ OutL) {
    extern __shared__ __align__(16) char smem[];
    const uint32_t sb = (uint32_t)__cvta_generic_to_shared(smem);
    const int tid = threadIdx.x;
    const int lane = tid & 31;
    const int warp_m = (tid >> 5) >> 1;   // 0..7, 16 rows
    const int warp_n = (tid >> 5) & 1;    // 0..1, 64 cols

    const uint32_t a_lane = (uint32_t)((lane & 15) * ROWB + (lane >> 4) * 16) +
                            (uint32_t)(warp_m * 16 * ROWB);
    const uint32_t b_lane = (uint32_t)(((lane & 7) + ((lane >> 4) & 1) * 8) * ROWB +
                                       ((lane >> 3) & 1) * 16) +
                            (uint32_t)(warp_n * 64 * ROWB);
    const uint32_t bH = sb + SM_B0 + b_lane;
    const uint32_t bL = sb + SM_B0 + TILEB + b_lane;

    float b0[8], b1[8];
#pragma unroll
    for (int nt = 0; nt < 8; nt++) {
        int col = warp_n * 64 + nt * 8 + (lane & 3) * 2;
        b0[nt] = __ldg(bias + col);
        b1[nt] = __ldg(bias + col + 1);
    }

    stage_B(sb + SM_B0, Bh, Bl, tid);
    int tile = blockIdx.x;
    if (tile < NTILES) stage_A_split(sb + SM_AH, Ah, Al, tile * 128, tid);
    cp_commit();
    cp_wait_all();
    __syncthreads();

    int buf = 0;
    for (; tile < NTILES; tile += PGRID) {
        const int m0 = tile * 128;
        const int nxt = tile + PGRID;
        if (nxt < NTILES)
            stage_A_split(sb + (buf ? SM_AH : SM_B1), Ah, Al, nxt * 128, tid);
        cp_commit();

        float acc[8][4];
        ACC_ZERO16(acc);
        const uint32_t aB = sb + (buf ? SM_B1 : SM_AH);
        mma_chunk16(acc, aB + a_lane, aB + TILEB + a_lane, bH, bL);

        int r0 = m0 + warp_m * 16 + (lane >> 2);
#pragma unroll
        for (int half = 0; half < 2; half++) {
            int r = r0 + half * 8;
            if (r >= NN) continue;
            const float* rrow = RESID ? (R + (size_t)r * 128) : nullptr;
#pragma unroll
            for (int nt = 0; nt < 8; nt++) {
                int col = warp_n * 64 + nt * 8 + (lane & 3) * 2;
                float x0 = acc[nt][half * 2 + 0] + b0[nt];
                float x1 = acc[nt][half * 2 + 1] + b1[nt];
                if (RESID) {
                    float2 rr = *(const float2*)(rrow + col);
                    x0 += rr.x; x1 += rr.y;
                }
                *(float2*)(OutF + (size_t)r * 128 + col) = make_float2(x0, x1);
                __nv_bfloat16 h0, l0, h1, l1;
                split_bf16(x0, h0, l0);
                split_bf16(x1, h1, l1);
                *(__nv_bfloat162*)(OutH + (size_t)r * 128 + col) =
                    __nv_bfloat162(h0, h1);
                *(__nv_bfloat162*)(OutL + (size_t)r * 128 + col) =
                    __nv_bfloat162(l0, l1);
            }
        }
        cp_wait_all();
        __syncthreads();
        buf ^= 1;
    }
}

// ---------------------------------------------------------------------------
// Persistent fused gate kernel, 512 threads:
//   u = gelu(h@Wsg + gh@Wnb + bsg + sev*bnb)
// ---------------------------------------------------------------------------
__global__ void __launch_bounds__(GTHREADS, 1) gemm_gate(
    const __nv_bfloat16* __restrict__ Hh, const __nv_bfloat16* __restrict__ Hl,
    const __nv_bfloat16* __restrict__ Gh, const __nv_bfloat16* __restrict__ Gl,
    const __nv_bfloat16* __restrict__ Wsgh, const __nv_bfloat16* __restrict__ Wsgl,
    const __nv_bfloat16* __restrict__ Wnbh, const __nv_bfloat16* __restrict__ Wnbl,
    const float* __restrict__ bsg, const float* __restrict__ bnb,
    const float* __restrict__ sev,
    __nv_bfloat16* __restrict__ OutH, __nv_bfloat16* __restrict__ OutL) {
    extern __shared__ __align__(16) char smem[];
    const uint32_t sb = (uint32_t)__cvta_generic_to_shared(smem);
    const int tid = threadIdx.x;
    const int lane = tid & 31;
    const int warp_m = (tid >> 5) >> 1;
    const int warp_n = (tid >> 5) & 1;

    const uint32_t a_lane = (uint32_t)((lane & 15) * ROWB + (lane >> 4) * 16) +
                            (uint32_t)(warp_m * 16 * ROWB);
    const uint32_t b_lane = (uint32_t)(((lane & 7) + ((lane >> 4) & 1) * 8) * ROWB +
                                       ((lane >> 3) & 1) * 16) +
                            (uint32_t)(warp_n * 64 * ROWB);
    const uint32_t aH = sb + SM_AH + a_lane;
    const uint32_t aL = sb + SM_AL + a_lane;

    float b0[8], b1[8], cv0[8], cv1[8];
#pragma unroll
    for (int nt = 0; nt < 8; nt++) {
        int col = warp_n * 64 + nt * 8 + (lane & 3) * 2;
        b0[nt] = __ldg(bsg + col);
        b1[nt] = __ldg(bsg + col + 1);
        cv0[nt] = __ldg(bnb + col);
        cv1[nt] = __ldg(bnb + col + 1);
    }

    stage_B(sb + SM_B0, Wsgh, Wsgl, tid);
    stage_B(sb + SM_B1, Wnbh, Wnbl, tid);
    int tile = blockIdx.x;
    if (tile < NTILES) stage_A_split(sb + SM_AH, Hh, Hl, tile * 128, tid);
    cp_commit();
    cp_wait_all();
    __syncthreads();

    for (; tile < NTILES; tile += PGRID) {
        const int m0 = tile * 128;

        float acc[8][4];
        ACC_ZERO16(acc);
        mma_chunk16(acc, aH, aL, sb + SM_B0 + b_lane, sb + SM_B0 + TILEB + b_lane);
        __syncthreads();

        stage_A_split(sb + SM_AH, Gh, Gl, m0, tid);
        cp_commit();
        cp_wait_all();
        __syncthreads();

        mma_chunk16(acc, aH, aL, sb + SM_B1 + b_lane, sb + SM_B1 + TILEB + b_lane);
        __syncthreads();

        const int nxt = tile + PGRID;
        if (nxt < NTILES) stage_A_split(sb + SM_AH, Hh, Hl, nxt * 128, tid);
        cp_commit();

        int r0 = m0 + warp_m * 16 + (lane >> 2);
#pragma unroll
        for (int half = 0; half < 2; half++) {
            int r = r0 + half * 8;
            if (r >= NN) continue;
            float sv = __ldg(sev + r);
#pragma unroll
            for (int nt = 0; nt < 8; nt++) {
                int col = warp_n * 64 + nt * 8 + (lane & 3) * 2;
                float x0 = gelu_f(fmaf(sv, cv0[nt], acc[nt][half * 2 + 0] + b0[nt]));
                float x1 = gelu_f(fmaf(sv, cv1[nt], acc[nt][half * 2 + 1] + b1[nt]));
                __nv_bfloat16 h0, l0, h1, l1;
                split_bf16(x0, h0, l0);
                split_bf16(x1, h1, l1);
                *(__nv_bfloat162*)(OutH + (size_t)r * 128 + col) =
                    __nv_bfloat162(h0, h1);
                *(__nv_bfloat162*)(OutL + (size_t)r * 128 + col) =
                    __nv_bfloat162(l0, l1);
            }
        }
        cp_wait_all();
        __syncthreads();
    }
}

// ---------------------------------------------------------------------------
// Combined weights (fp32, exact)
// ---------------------------------------------------------------------------
__global__ void k_wcomb(const float* __restrict__ nw, const float* __restrict__ sw,
                        const float* __restrict__ gw1) {
    int idx = blockIdx.x * blockDim.x + threadIdx.x;
    if (idx >= 4 * 16384) return;
    int which = idx >> 15;            // 0 = Wnb, 1 = Wsg
    int sub = idx & 32767;
    int l = sub >> 14;
    int k = (sub >> 7) & 127;
    int n = sub & 127;
    const float* a;
    const float* b;
    if (which == 0) {
        a = nw + (size_t)l * 16384 + k * 128;
        b = gw1 + (size_t)l * 32768 + 16384 + n;
    } else {
        a = sw + (size_t)l * 16384 + k * 128;
        b = gw1 + (size_t)l * 32768 + n;
    }
    float s = 0.0f;
#pragma unroll 8
    for (int m = 0; m < 128; m++) s = fmaf(a[m], b[(size_t)m * 128], s);
    if (which == 0) g_wnb[sub] = s;
    else            g_wsg[sub] = s;
}
__global__ void k_bcomb(const float* __restrict__ nbw, const float* __restrict__ sb,
                        const float* __restrict__ gb1, const float* __restrict__ gw1) {
    int idx = blockIdx.x * blockDim.x + threadIdx.x;
    if (idx >= 4 * CC) return;
    int which = idx >> 8;             // 0 = bnb, 1 = bsg
    int l = (idx >> 7) & 1, n = idx & 127;
    float s = 0.0f;
    if (which == 0) {
#pragma unroll 8
        for (int m = 0; m < 128; m++)
            s = fmaf(nbw[l * 128 + m],
                     gw1[(size_t)l * 32768 + 16384 + (size_t)m * 128 + n], s);
        g_bnb[l * CC + n] = s;
    } else {
#pragma unroll 8
        for (int m = 0; m < 128; m++)
            s = fmaf(sb[l * 128 + m], gw1[(size_t)l * 32768 + (size_t)m * 128 + n], s);
        g_bsg[l * CC + n] = s + gb1[l * 128 + n];
    }
}

// ---------------------------------------------------------------------------
// Weight conversion: fp32 W[K,N] -> bf16 hi/lo B[N,K]
// ---------------------------------------------------------------------------
__global__ void wconv_kernel(const float* __restrict__ lw2,
                             const float* __restrict__ gw2) {
    int idx = blockIdx.x * blockDim.x + threadIdx.x;
    if (idx >= WSLOTS * 16384) return;
    int slot = idx >> 14;
    int within = idx & 16383;
    int n = within >> 7;
    int k = within & 127;
    const float* src;
    if (slot == 0) {
        src = lw2 + k * 128 + n;
    } else {
        int l = (slot - 1) / 3, j = (slot - 1) % 3;
        if (j == 0)      src = g_wsg + (size_t)l * 16384 + k * 128 + n;
        else if (j == 1) src = g_wnb + (size_t)l * 16384 + k * 128 + n;
        else             src = gw2 + (size_t)l * 16384 + k * 128 + n;
    }
    __nv_bfloat16 hi, lo;
    split_bf16(*src, hi, lo);
    g_wbh[idx] = hi;
    g_wbl[idx] = lo;
}

// ---------------------------------------------------------------------------
// CSR build
// ---------------------------------------------------------------------------
__global__ void k_zero_cnt() {
    int i = blockIdx.x * blockDim.x + threadIdx.x;
    if (i < NN) g_cnt[i] = 0;
}
__global__ void k_count(const int* __restrict__ ei) {
    int e = blockIdx.x * blockDim.x + threadIdx.x;
    if (e < EE) atomicAdd(&g_cnt[ei[e]], 1);
}
__global__ void k_blocksum() {
    __shared__ int sh[256];
    int i = blockIdx.x * 256 + threadIdx.x;
    int v = (i < NN) ? g_cnt[i] : 0;
    sh[threadIdx.x] = v;
    __syncthreads();
    for (int s = 128; s; s >>= 1) {
        if (threadIdx.x < s) sh[threadIdx.x] += sh[threadIdx.x + s];
        __syncthreads();
    }
    if (threadIdx.x == 0) g_bsum[blockIdx.x] = sh[0];
}
__global__ void k_scan_bsum() {
    __shared__ int sh[512];
    int t = threadIdx.x;
    sh[t] = (t < SCAN_BLOCKS) ? g_bsum[t] : 0;
    __syncthreads();
    for (int off = 1; off < 512; off <<= 1) {
        int v = (t >= off) ? sh[t - off] : 0;
        __syncthreads();
        sh[t] += v;
        __syncthreads();
    }
    if (t < SCAN_BLOCKS) g_boff[t] = sh[t] - g_bsum[t];
}
__global__ void k_rowstart() {
    __shared__ int sh[256];
    int i = blockIdx.x * 256 + threadIdx.x;
    int v = (i < NN) ? g_cnt[i] : 0;
    sh[threadIdx.x] = v;
    __syncthreads();
    for (int off = 1; off < 256; off <<= 1) {
        int u = (threadIdx.x >= off) ? sh[threadIdx.x - off] : 0;
        __syncthreads();
        sh[threadIdx.x] += u;
        __syncthreads();
    }
    if (i < NN) {
        int excl = sh[threadIdx.x] - v + g_boff[blockIdx.x];
        g_rowstart[i] = excl;
        g_cursor[i] = excl;
        if (i == NN - 1) g_rowstart[NN] = excl + v;
    }
}
__global__ void k_fill(const int* __restrict__ ei, const float* __restrict__ ev) {
    int e = blockIdx.x * blockDim.x + threadIdx.x;
    if (e >= EE) return;
    int row = ei[e];
    int pos = atomicAdd(&g_cursor[row], 1);
    g_ecol[pos] = ei[EE + e];
    g_eval[pos] = ev[e];
}

// ---------------------------------------------------------------------------
// Pull aggregation of h: gh[r] = sum ev*h[col] (split); sev[r] = sum ev.
// ---------------------------------------------------------------------------
__global__ void k_aggr() {
    int r = blockIdx.x * 8 + (threadIdx.x >> 5);
    if (r >= NN) return;
    int lane = threadIdx.x & 31;
    int s = g_rowstart[r];
    int e = g_rowstart[r + 1];
    float acc[4] = {0.f, 0.f, 0.f, 0.f};
    float sev = 0.f;
    for (int j = s; j < e; j++) {
        int c = __ldg(&g_ecol[j]);
        float v = __ldg(&g_eval[j]);
        sev += v;
        const float* srow = g_h + (size_t)c * CC + lane;
        acc[0] = fmaf(__ldg(srow),      v, acc[0]);
        acc[1] = fmaf(__ldg(srow + 32), v, acc[1]);
        acc[2] = fmaf(__ldg(srow + 64), v, acc[2]);
        acc[3] = fmaf(__ldg(srow + 96), v, acc[3]);
    }
#pragma unroll
    for (int i = 0; i < 4; i++) {
        __nv_bfloat16 hi, lo;
        split_bf16(acc[i], hi, lo);
        g_agh[(size_t)r * CC + lane + i * 32] = hi;
        g_agl[(size_t)r * CC + lane + i * 32] = lo;
    }
    if (lane == 0) g_sev[r] = sev;
}

// ---------------------------------------------------------------------------
// Lift stage 1 + LayerNorm
// ---------------------------------------------------------------------------
__global__ void lift_hidden_kernel(const float* __restrict__ x,
                                   const float* __restrict__ w1,
                                   const float* __restrict__ b1) {
    int idx = blockIdx.x * blockDim.x + threadIdx.x;
    if (idx >= NN * CC) return;
    int n = idx >> 7;
    int c = idx & 127;
    const float* xr = x + (size_t)n * 9 + 3;
    float acc = b1[c];
#pragma unroll
    for (int i = 0; i < 6; i++)
        acc = fmaf(xr[i], w1[i * CC + c], acc);
    float v = gelu_f(acc);
    __nv_bfloat16 hi, lo;
    split_bf16(v, hi, lo);
    g_uh[idx] = hi;
    g_ul[idx] = lo;
}

__global__ void ln_kernel(const float* __restrict__ h,
                          const float* __restrict__ g,
                          const float* __restrict__ b,
                          float* __restrict__ out) {
    int n = blockIdx.x * 8 + (threadIdx.x >> 5);
    if (n >= NN) return;
    int lane = threadIdx.x & 31;
    const float* r = h + (size_t)n * CC;
    float v[4];
    float s = 0.f;
#pragma unroll
    for (int i = 0; i < 4; i++) { v[i] = r[lane + i * 32]; s += v[i]; }
#pragma unroll
    for (int o = 16; o; o >>= 1) s += __shfl_xor_sync(0xffffffffu, s, o);
    float mu = s * (1.f / 128.f);
    float q = 0.f;
#pragma unroll
    for (int i = 0; i < 4; i++) { float d = v[i] - mu; q = fmaf(d, d, q); }
#pragma unroll
    for (int o = 16; o; o >>= 1) q += __shfl_xor_sync(0xffffffffu, q, o);
    float inv = rsqrtf(q * (1.f / 128.f) + 1e-5f);
#pragma unroll
    for (int i = 0; i < 4; i++) {
        int c = lane + i * 32;
        out[(size_t)n * CC + c] = fmaf((v[i] - mu) * inv, g[c], b[c]);
    }
}

// ---------------------------------------------------------------------------
extern "C" void kernel_launch(void* const* d_in, const int* in_sizes, int n_in,
                              void* d_out, int out_size) {
    const float* x   = (const float*)d_in[0];
    const int*   ei  = (const int*)d_in[1];
    const float* ev  = (const float*)d_in[2];
    const float* lw1 = (const float*)d_in[3];
    const float* lb1 = (const float*)d_in[4];
    const float* lw2 = (const float*)d_in[5];
    const float* lb2 = (const float*)d_in[6];
    const float* sw  = (const float*)d_in[7];
    const float* sb  = (const float*)d_in[8];
    const float* nw  = (const float*)d_in[9];
    const float* nbw = (const float*)d_in[10];
    const float* gw1 = (const float*)d_in[11];
    const float* gb1 = (const float*)d_in[12];
    const float* gw2 = (const float*)d_in[13];
    const float* gb2 = (const float*)d_in[14];
    const float* ng  = (const float*)d_in[15];
    const float* nbt = (const float*)d_in[16];
    float* out = (float*)d_out;

    float *h, *sev, *bnb, *bsg;
    cudaGetSymbolAddress((void**)&h, g_h);
    cudaGetSymbolAddress((void**)&sev, g_sev);
    cudaGetSymbolAddress((void**)&bnb, g_bnb);
    cudaGetSymbolAddress((void**)&bsg, g_bsg);
    __nv_bfloat16 *wbh, *wbl, *uh, *ul, *hh, *hl, *agh, *agl;
    cudaGetSymbolAddress((void**)&wbh, g_wbh);
    cudaGetSymbolAddress((void**)&wbl, g_wbl);
    cudaGetSymbolAddress((void**)&uh, g_uh);
    cudaGetSymbolAddress((void**)&ul, g_ul);
    cudaGetSymbolAddress((void**)&hh, g_hh);
    cudaGetSymbolAddress((void**)&hl, g_hl);
    cudaGetSymbolAddress((void**)&agh, g_agh);
    cudaGetSymbolAddress((void**)&agl, g_agl);

    cudaFuncSetAttribute(gemm_pers<0>, cudaFuncAttributeMaxDynamicSharedMemorySize, SM_TOTAL);
    cudaFuncSetAttribute(gemm_pers<1>, cudaFuncAttributeMaxDynamicSharedMemorySize, SM_TOTAL);
    cudaFuncSetAttribute(gemm_gate, cudaFuncAttributeMaxDynamicSharedMemorySize, SM_TOTAL);

    // Fork/join resources (capture-legal; validated in R14)
    cudaStream_t s2;
    cudaStreamCreateWithFlags(&s2, cudaStreamNonBlocking);
    cudaEvent_t evF, evJ;
    cudaEventCreateWithFlags(&evF, cudaEventDisableTiming);
    cudaEventCreateWithFlags(&evJ, cudaEventDisableTiming);

    // ---- Fork: CSR build on s2 || weight prep + lift on main ----
    cudaEventRecord(evF, 0);
    cudaStreamWaitEvent(s2, evF, 0);

    k_zero_cnt<<<SCAN_BLOCKS, 256, 0, s2>>>();
    k_count<<<(EE + 255) / 256, 256, 0, s2>>>(ei);
    k_blocksum<<<SCAN_BLOCKS, 256, 0, s2>>>();
    k_scan_bsum<<<1, 512, 0, s2>>>();
    k_rowstart<<<SCAN_BLOCKS, 256, 0, s2>>>();
    k_fill<<<(EE + 255) / 256, 256, 0, s2>>>(ei, ev);
    cudaEventRecord(evJ, s2);

    k_wcomb<<<(4 * 16384 + 255) / 256, 256>>>(nw, sw, gw1);
    k_bcomb<<<2, 256>>>(nbw, sb, gb1, gw1);
    wconv_kernel<<<(WSLOTS * 16384 + 255) / 256, 256>>>(lw2, gw2);
    lift_hidden_kernel<<<(NN * CC + 255) / 256, 256>>>(x, lw1, lb1);
    gemm_pers<0><<<PGRID, GTHREADS, SM_TOTAL>>>(uh, ul, wbh, wbl, lb2, nullptr,
                                                h, hh, hl);

    cudaStreamWaitEvent(0, evJ, 0);   // join: CSR ready

    for (int l = 0; l < 2; l++) {
        const __nv_bfloat16* wsgh = wbh + (size_t)(1 + 3 * l) * 16384;
        const __nv_bfloat16* wsgl = wbl + (size_t)(1 + 3 * l) * 16384;
        const __nv_bfloat16* wnbh = wbh + (size_t)(2 + 3 * l) * 16384;
        const __nv_bfloat16* wnbl = wbl + (size_t)(2 + 3 * l) * 16384;
        const __nv_bfloat16* g2h  = wbh + (size_t)(3 + 3 * l) * 16384;
        const __nv_bfloat16* g2l  = wbl + (size_t)(3 + 3 * l) * 16384;

        // gh (split) + sev = pull-gather of h
        k_aggr<<<(NN + 7) / 8, 256>>>();
        // u = gelu(h@Wsg + gh@Wnb + bsg + sev*bnb)  (fused, both B resident)
        gemm_gate<<<PGRID, GTHREADS, SM_TOTAL>>>(hh, hl, agh, agl,
                                                 wsgh, wsgl, wnbh, wnbl,
                                                 bsg + l * CC, bnb + l * CC, sev,
                                                 uh, ul);
        // h = h + u @ Wg2 + bg2  (fp32 + split)
        gemm_pers<1><<<PGRID, GTHREADS, SM_TOTAL>>>(uh, ul, g2h, g2l,
                                                    gb2 + l * CC, h, h, hh, hl);
    }

    ln_kernel<<<(NN + 7) / 8, 256>>>(h, ng, nbt, out);
}

// round 16
// speedup vs baseline: 1.4305x; 1.3820x over previous
#include <cuda_runtime.h>
#include <cuda_fp16.h>
#include <math.h>
#include <stdint.h>

#define NN 100000
#define EE 1600000
#define CC 128
#define NTILES ((NN + 127) / 128)       // 782
#define PGRID 148
#define GTHREADS 512
#define SCAN_BLOCKS ((NN + 255) / 256)  // 391

// ---------------------------------------------------------------------------
// Scratch (allocation-free rule: __device__ globals)
// ---------------------------------------------------------------------------
__device__ float g_h[(size_t)NN * CC];     // fp32 h (gather source + resid + LN)

__device__ __half g_u16[(size_t)NN * CC];   // lift-hidden / u (fp16)
__device__ __half g_h16[(size_t)NN * CC];   // h (fp16)
__device__ __half g_ag16[(size_t)NN * CC];  // gathered h (fp16)

__device__ float g_sev[NN];                // per-row sum of edge values
__device__ float g_wnb[2 * 16384];         // Wn @ W1b (fp32)
__device__ float g_wsg[2 * 16384];         // Ws @ W1a (fp32)
__device__ float g_bnb[2 * CC];            // bn @ W1b
__device__ float g_bsg[2 * CC];            // bs @ W1a + bg1

// CSR scratch
__device__ int   g_cnt[NN];
__device__ int   g_rowstart[NN + 1];
__device__ int   g_cursor[NN];
__device__ int   g_bsum[SCAN_BLOCKS];
__device__ int   g_boff[SCAN_BLOCKS];
__device__ int   g_ecol[EE];
__device__ float g_eval[EE];

// Pre-converted fp16 weight tiles, layout [slot][n][k]
// slots: [0]=lift2; per layer l: [1+3l]=Wsg, [2+3l]=Wnb, [3+3l]=gate2.
#define WSLOTS 7
__device__ __half g_wb[(size_t)WSLOTS * 16384];

__device__ __forceinline__ float gelu_f(float v) {
    return 0.5f * v * (1.0f + erff(v * 0.7071067811865475f));
}

// ---------------------------------------------------------------------------
// mma.sync / cp.async helpers
// ---------------------------------------------------------------------------
__device__ __forceinline__ void ldsm_x4(uint32_t* r, uint32_t addr) {
    asm volatile("ldmatrix.sync.aligned.m8n8.x4.shared.b16 {%0,%1,%2,%3}, [%4];"
                 : "=r"(r[0]), "=r"(r[1]), "=r"(r[2]), "=r"(r[3]) : "r"(addr));
}
__device__ __forceinline__ void mma_f16(float* d, const uint32_t* a, const uint32_t* b) {
    asm volatile(
        "mma.sync.aligned.m16n8k16.row.col.f32.f16.f16.f32 "
        "{%0,%1,%2,%3}, {%4,%5,%6,%7}, {%8,%9}, {%0,%1,%2,%3};"
        : "+f"(d[0]), "+f"(d[1]), "+f"(d[2]), "+f"(d[3])
        : "r"(a[0]), "r"(a[1]), "r"(a[2]), "r"(a[3]), "r"(b[0]), "r"(b[1]));
}
__device__ __forceinline__ void cp16(uint32_t dst, const void* src, int srcsize) {
    asm volatile("cp.async.cg.shared.global [%0], [%1], 16, %2;"
                 :: "r"(dst), "l"(src), "r"(srcsize) : "memory");
}
__device__ __forceinline__ void cp_commit() {
    asm volatile("cp.async.commit_group;" ::: "memory");
}
__device__ __forceinline__ void cp_wait_all() {
    asm volatile("cp.async.wait_group 0;" ::: "memory");
}

// ---------------------------------------------------------------------------
// Smem layout: tiles of 128 rows x 256B (+16B pad) = 34816B.
// ---------------------------------------------------------------------------
#define ROWB 272
#define TILEB (128 * ROWB)          // 34816
// gate: 6 slots (Wsg, Wnb, h0, gh0, h1, gh1); pers: 3 slots (B, A0, A1)
#define SM_GATE (6 * TILEB)         // 208896
#define SM_PERS (3 * TILEB)         // 104448

// fp16 single-pass MMA over one staged 128-K tile; warp tile 16x64.
__device__ __forceinline__ void mma_chunk16(float acc[8][4], uint32_t aB,
                                            uint32_t bB) {
#pragma unroll
    for (int ks = 0; ks < 8; ks++) {
        uint32_t a[4], b[4][4];
        ldsm_x4(a, aB + ks * 32);
#pragma unroll
        for (int np = 0; np < 4; np++)
            ldsm_x4(b[np], bB + ks * 32 + np * 16 * ROWB);
#pragma unroll
        for (int nt = 0; nt < 8; nt++) {
            uint32_t bb[2] = { b[nt >> 1][(nt & 1) * 2], b[nt >> 1][(nt & 1) * 2 + 1] };
            mma_f16(acc[nt], a, bb);
        }
    }
}

#define ACC_ZERO16(acc)                                 \
    _Pragma("unroll")                                   \
    for (int nt = 0; nt < 8; nt++)                      \
        _Pragma("unroll")                               \
        for (int e = 0; e < 4; e++) acc[nt][e] = 0.0f;

// Stage one fp16 tile: 2048 x 16B chunks, 4 per thread (512 threads).
__device__ __forceinline__ void stage_A16(uint32_t abase, const __half* __restrict__ A,
                                          int m0, int tid) {
#pragma unroll
    for (int i = 0; i < 4; i++) {
        int ci = tid + i * GTHREADS;
        int row = ci >> 4, ch = ci & 15;
        int gm = m0 + row;
        int ss = (gm < NN) ? 16 : 0;
        int gms = (gm < NN) ? gm : (NN - 1);
        cp16(abase + (uint32_t)(row * ROWB + ch * 16),
             A + (size_t)gms * 128 + ch * 8, ss);
    }
}
__device__ __forceinline__ void stage_B16(uint32_t bbase, const __half* __restrict__ B,
                                          int tid) {
#pragma unroll
    for (int i = 0; i < 4; i++) {
        int ci = tid + i * GTHREADS;
        int row = ci >> 4, ch = ci & 15;
        cp16(bbase + (uint32_t)(row * ROWB + ch * 16), B + ci * 8, 16);
    }
}

// ---------------------------------------------------------------------------
// Persistent GEMM, 512 threads. RESID: 0 none, 1 post-act.
// Writes fp32 (+resid) and fp16 copies.
// ---------------------------------------------------------------------------
template <int RESID>
__global__ void __launch_bounds__(GTHREADS, 1) gemm_pers(
    const __half* __restrict__ A16, const __half* __restrict__ B16,
    const float* __restrict__ bias, const float* __restrict__ R,
    float* __restrict__ OutF, __half* __restrict__ Out16) {
    extern __shared__ __align__(16) char smem[];
    const uint32_t sb = (uint32_t)__cvta_generic_to_shared(smem);
    const int tid = threadIdx.x;
    const int lane = tid & 31;
    const int warp_m = (tid >> 5) >> 1;   // 0..7, 16 rows
    const int warp_n = (tid >> 5) & 1;    // 0..1, 64 cols

    const uint32_t a_lane = (uint32_t)((lane & 15) * ROWB + (lane >> 4) * 16) +
                            (uint32_t)(warp_m * 16 * ROWB);
    const uint32_t b_lane = (uint32_t)(((lane & 7) + ((lane >> 4) & 1) * 8) * ROWB +
                                       ((lane >> 3) & 1) * 16) +
                            (uint32_t)(warp_n * 64 * ROWB);
    const uint32_t bB = sb + b_lane;            // B in slot 0

    float b0[8], b1[8];
#pragma unroll
    for (int nt = 0; nt < 8; nt++) {
        int col = warp_n * 64 + nt * 8 + (lane & 3) * 2;
        b0[nt] = __ldg(bias + col);
        b1[nt] = __ldg(bias + col + 1);
    }

    stage_B16(sb, B16, tid);
    int tile = blockIdx.x;
    if (tile < NTILES) stage_A16(sb + TILEB, A16, tile * 128, tid);
    cp_commit();
    cp_wait_all();
    __syncthreads();

    int buf = 0;
    for (; tile < NTILES; tile += PGRID) {
        const int m0 = tile * 128;
        const int nxt = tile + PGRID;
        if (nxt < NTILES)
            stage_A16(sb + (buf ? TILEB : 2 * TILEB), A16, nxt * 128, tid);
        cp_commit();

        float acc[8][4];
        ACC_ZERO16(acc);
        mma_chunk16(acc, sb + (buf ? 2 * TILEB : TILEB) + a_lane, bB);

        int r0 = m0 + warp_m * 16 + (lane >> 2);
#pragma unroll
        for (int half = 0; half < 2; half++) {
            int r = r0 + half * 8;
            if (r >= NN) continue;
            const float* rrow = RESID ? (R + (size_t)r * 128) : nullptr;
#pragma unroll
            for (int nt = 0; nt < 8; nt++) {
                int col = warp_n * 64 + nt * 8 + (lane & 3) * 2;
                float x0 = acc[nt][half * 2 + 0] + b0[nt];
                float x1 = acc[nt][half * 2 + 1] + b1[nt];
                if (RESID) {
                    float2 rr = *(const float2*)(rrow + col);
                    x0 += rr.x; x1 += rr.y;
                }
                *(float2*)(OutF + (size_t)r * 128 + col) = make_float2(x0, x1);
                *(__half2*)(Out16 + (size_t)r * 128 + col) =
                    __floats2half2_rn(x0, x1);
            }
        }
        cp_wait_all();
        __syncthreads();
        buf ^= 1;
    }
}

// ---------------------------------------------------------------------------
// Persistent fused gate kernel, 512 threads, fully double-buffered:
//   u = gelu(h@Wsg + gh@Wnb + bsg + sev*bnb)
// Slots: 0=Wsg, 1=Wnb, 2=h0, 3=gh0, 4=h1, 5=gh1.
// ---------------------------------------------------------------------------
__global__ void __launch_bounds__(GTHREADS, 1) gemm_gate(
    const __half* __restrict__ H16, const __half* __restrict__ G16,
    const __half* __restrict__ Wsg, const __half* __restrict__ Wnb,
    const float* __restrict__ bsg, const float* __restrict__ bnb,
    const float* __restrict__ sev, __half* __restrict__ Out16) {
    extern __shared__ __align__(16) char smem[];
    const uint32_t sb = (uint32_t)__cvta_generic_to_shared(smem);
    const int tid = threadIdx.x;
    const int lane = tid & 31;
    const int warp_m = (tid >> 5) >> 1;
    const int warp_n = (tid >> 5) & 1;

    const uint32_t a_lane = (uint32_t)((lane & 15) * ROWB + (lane >> 4) * 16) +
                            (uint32_t)(warp_m * 16 * ROWB);
    const uint32_t b_lane = (uint32_t)(((lane & 7) + ((lane >> 4) & 1) * 8) * ROWB +
                                       ((lane >> 3) & 1) * 16) +
                            (uint32_t)(warp_n * 64 * ROWB);
    const uint32_t bSG = sb + b_lane;
    const uint32_t bNB = sb + TILEB + b_lane;

    float b0[8], b1[8], cv0[8], cv1[8];
#pragma unroll
    for (int nt = 0; nt < 8; nt++) {
        int col = warp_n * 64 + nt * 8 + (lane & 3) * 2;
        b0[nt] = __ldg(bsg + col);
        b1[nt] = __ldg(bsg + col + 1);
        cv0[nt] = __ldg(bnb + col);
        cv1[nt] = __ldg(bnb + col + 1);
    }

    stage_B16(sb, Wsg, tid);
    stage_B16(sb + TILEB, Wnb, tid);
    int tile = blockIdx.x;
    if (tile < NTILES) {
        stage_A16(sb + 2 * TILEB, H16, tile * 128, tid);
        stage_A16(sb + 3 * TILEB, G16, tile * 128, tid);
    }
    cp_commit();
    cp_wait_all();
    __syncthreads();

    int buf = 0;
    for (; tile < NTILES; tile += PGRID) {
        const int m0 = tile * 128;
        const int nxt = tile + PGRID;
        if (nxt < NTILES) {
            stage_A16(sb + (buf ? 2 : 4) * TILEB, H16, nxt * 128, tid);
            stage_A16(sb + (buf ? 3 : 5) * TILEB, G16, nxt * 128, tid);
        }
        cp_commit();

        float acc[8][4];
        ACC_ZERO16(acc);
        const uint32_t aH = sb + (buf ? 4 : 2) * TILEB + a_lane;
        const uint32_t aG = sb + (buf ? 5 : 3) * TILEB + a_lane;
        mma_chunk16(acc, aH, bSG);
        mma_chunk16(acc, aG, bNB);

        int r0 = m0 + warp_m * 16 + (lane >> 2);
#pragma unroll
        for (int half = 0; half < 2; half++) {
            int r = r0 + half * 8;
            if (r >= NN) continue;
            float sv = __ldg(sev + r);
#pragma unroll
            for (int nt = 0; nt < 8; nt++) {
                int col = warp_n * 64 + nt * 8 + (lane & 3) * 2;
                float x0 = gelu_f(fmaf(sv, cv0[nt], acc[nt][half * 2 + 0] + b0[nt]));
                float x1 = gelu_f(fmaf(sv, cv1[nt], acc[nt][half * 2 + 1] + b1[nt]));
                *(__half2*)(Out16 + (size_t)r * 128 + col) =
                    __floats2half2_rn(x0, x1);
            }
        }
        cp_wait_all();
        __syncthreads();
        buf ^= 1;
    }
}

// ---------------------------------------------------------------------------
// Combined weights (fp32, exact)
// ---------------------------------------------------------------------------
__global__ void k_wcomb(const float* __restrict__ nw, const float* __restrict__ sw,
                        const float* __restrict__ gw1) {
    int idx = blockIdx.x * blockDim.x + threadIdx.x;
    if (idx >= 4 * 16384) return;
    int which = idx >> 15;            // 0 = Wnb, 1 = Wsg
    int sub = idx & 32767;
    int l = sub >> 14;
    int k = (sub >> 7) & 127;
    int n = sub & 127;
    const float* a;
    const float* b;
    if (which == 0) {
        a = nw + (size_t)l * 16384 + k * 128;
        b = gw1 + (size_t)l * 32768 + 16384 + n;
    } else {
        a = sw + (size_t)l * 16384 + k * 128;
        b = gw1 + (size_t)l * 32768 + n;
    }
    float s = 0.0f;
#pragma unroll 8
    for (int m = 0; m < 128; m++) s = fmaf(a[m], b[(size_t)m * 128], s);
    if (which == 0) g_wnb[sub] = s;
    else            g_wsg[sub] = s;
}
__global__ void k_bcomb(const float* __restrict__ nbw, const float* __restrict__ sb,
                        const float* __restrict__ gb1, const float* __restrict__ gw1) {
    int idx = blockIdx.x * blockDim.x + threadIdx.x;
    if (idx >= 4 * CC) return;
    int which = idx >> 8;             // 0 = bnb, 1 = bsg
    int l = (idx >> 7) & 1, n = idx & 127;
    float s = 0.0f;
    if (which == 0) {
#pragma unroll 8
        for (int m = 0; m < 128; m++)
            s = fmaf(nbw[l * 128 + m],
                     gw1[(size_t)l * 32768 + 16384 + (size_t)m * 128 + n], s);
        g_bnb[l * CC + n] = s;
    } else {
#pragma unroll 8
        for (int m = 0; m < 128; m++)
            s = fmaf(sb[l * 128 + m], gw1[(size_t)l * 32768 + (size_t)m * 128 + n], s);
        g_bsg[l * CC + n] = s + gb1[l * 128 + n];
    }
}

// ---------------------------------------------------------------------------
// Weight conversion: fp32 W[K,N] -> fp16 B[N,K]
// ---------------------------------------------------------------------------
__global__ void wconv_kernel(const float* __restrict__ lw2,
                             const float* __restrict__ gw2) {
    int idx = blockIdx.x * blockDim.x + threadIdx.x;
    if (idx >= WSLOTS * 16384) return;
    int slot = idx >> 14;
    int within = idx & 16383;
    int n = within >> 7;
    int k = within & 127;
    const float* src;
    if (slot == 0) {
        src = lw2 + k * 128 + n;
    } else {
        int l = (slot - 1) / 3, j = (slot - 1) % 3;
        if (j == 0)      src = g_wsg + (size_t)l * 16384 + k * 128 + n;
        else if (j == 1) src = g_wnb + (size_t)l * 16384 + k * 128 + n;
        else             src = gw2 + (size_t)l * 16384 + k * 128 + n;
    }
    g_wb[idx] = __float2half_rn(*src);
}

// ---------------------------------------------------------------------------
// CSR build
// ---------------------------------------------------------------------------
__global__ void k_zero_cnt() {
    int i = blockIdx.x * blockDim.x + threadIdx.x;
    if (i < NN) g_cnt[i] = 0;
}
__global__ void k_count(const int* __restrict__ ei) {
    int e = blockIdx.x * blockDim.x + threadIdx.x;
    if (e < EE) atomicAdd(&g_cnt[ei[e]], 1);
}
__global__ void k_blocksum() {
    __shared__ int sh[256];
    int i = blockIdx.x * 256 + threadIdx.x;
    int v = (i < NN) ? g_cnt[i] : 0;
    sh[threadIdx.x] = v;
    __syncthreads();
    for (int s = 128; s; s >>= 1) {
        if (threadIdx.x < s) sh[threadIdx.x] += sh[threadIdx.x + s];
        __syncthreads();
    }
    if (threadIdx.x == 0) g_bsum[blockIdx.x] = sh[0];
}
__global__ void k_scan_bsum() {
    __shared__ int sh[512];
    int t = threadIdx.x;
    sh[t] = (t < SCAN_BLOCKS) ? g_bsum[t] : 0;
    __syncthreads();
    for (int off = 1; off < 512; off <<= 1) {
        int v = (t >= off) ? sh[t - off] : 0;
        __syncthreads();
        sh[t] += v;
        __syncthreads();
    }
    if (t < SCAN_BLOCKS) g_boff[t] = sh[t] - g_bsum[t];
}
__global__ void k_rowstart() {
    __shared__ int sh[256];
    int i = blockIdx.x * 256 + threadIdx.x;
    int v = (i < NN) ? g_cnt[i] : 0;
    sh[threadIdx.x] = v;
    __syncthreads();
    for (int off = 1; off < 256; off <<= 1) {
        int u = (threadIdx.x >= off) ? sh[threadIdx.x - off] : 0;
        __syncthreads();
        sh[threadIdx.x] += u;
        __syncthreads();
    }
    if (i < NN) {
        int excl = sh[threadIdx.x] - v + g_boff[blockIdx.x];
        g_rowstart[i] = excl;
        g_cursor[i] = excl;
        if (i == NN - 1) g_rowstart[NN] = excl + v;
    }
}
__global__ void k_fill(const int* __restrict__ ei, const float* __restrict__ ev) {
    int e = blockIdx.x * blockDim.x + threadIdx.x;
    if (e >= EE) return;
    int row = ei[e];
    int pos = atomicAdd(&g_cursor[row], 1);
    g_ecol[pos] = ei[EE + e];
    g_eval[pos] = ev[e];
}

// ---------------------------------------------------------------------------
// Pull aggregation of h (fp32 source): gh (fp16) + sev.
// ---------------------------------------------------------------------------
__global__ void k_aggr() {
    int r = blockIdx.x * 8 + (threadIdx.x >> 5);
    if (r >= NN) return;
    int lane = threadIdx.x & 31;
    int s = g_rowstart[r];
    int e = g_rowstart[r + 1];
    float acc[4] = {0.f, 0.f, 0.f, 0.f};
    float sev = 0.f;
    for (int j = s; j < e; j++) {
        int c = __ldg(&g_ecol[j]);
        float v = __ldg(&g_eval[j]);
        sev += v;
        const float* srow = g_h + (size_t)c * CC + lane;
        acc[0] = fmaf(__ldg(srow),      v, acc[0]);
        acc[1] = fmaf(__ldg(srow + 32), v, acc[1]);
        acc[2] = fmaf(__ldg(srow + 64), v, acc[2]);
        acc[3] = fmaf(__ldg(srow + 96), v, acc[3]);
    }
#pragma unroll
    for (int i = 0; i < 4; i++)
        g_ag16[(size_t)r * CC + lane + i * 32] = __float2half_rn(acc[i]);
    if (lane == 0) g_sev[r] = sev;
}

// ---------------------------------------------------------------------------
// Lift stage 1 + LayerNorm
// ---------------------------------------------------------------------------
__global__ void lift_hidden_kernel(const float* __restrict__ x,
                                   const float* __restrict__ w1,
                                   const float* __restrict__ b1) {
    int idx = blockIdx.x * blockDim.x + threadIdx.x;
    if (idx >= NN * CC) return;
    int n = idx >> 7;
    int c = idx & 127;
    const float* xr = x + (size_t)n * 9 + 3;
    float acc = b1[c];
#pragma unroll
    for (int i = 0; i < 6; i++)
        acc = fmaf(xr[i], w1[i * CC + c], acc);
    g_u16[idx] = __float2half_rn(gelu_f(acc));
}

__global__ void ln_kernel(const float* __restrict__ h,
                          const float* __restrict__ g,
                          const float* __restrict__ b,
                          float* __restrict__ out) {
    int n = blockIdx.x * 8 + (threadIdx.x >> 5);
    if (n >= NN) return;
    int lane = threadIdx.x & 31;
    const float* r = h + (size_t)n * CC;
    float v[4];
    float s = 0.f;
#pragma unroll
    for (int i = 0; i < 4; i++) { v[i] = r[lane + i * 32]; s += v[i]; }
#pragma unroll
    for (int o = 16; o; o >>= 1) s += __shfl_xor_sync(0xffffffffu, s, o);
    float mu = s * (1.f / 128.f);
    float q = 0.f;
#pragma unroll
    for (int i = 0; i < 4; i++) { float d = v[i] - mu; q = fmaf(d, d, q); }
#pragma unroll
    for (int o = 16; o; o >>= 1) q += __shfl_xor_sync(0xffffffffu, q, o);
    float inv = rsqrtf(q * (1.f / 128.f) + 1e-5f);
#pragma unroll
    for (int i = 0; i < 4; i++) {
        int c = lane + i * 32;
        out[(size_t)n * CC + c] = fmaf((v[i] - mu) * inv, g[c], b[c]);
    }
}

// ---------------------------------------------------------------------------
extern "C" void kernel_launch(void* const* d_in, const int* in_sizes, int n_in,
                              void* d_out, int out_size) {
    const float* x   = (const float*)d_in[0];
    const int*   ei  = (const int*)d_in[1];
    const float* ev  = (const float*)d_in[2];
    const float* lw1 = (const float*)d_in[3];
    const float* lb1 = (const float*)d_in[4];
    const float* lw2 = (const float*)d_in[5];
    const float* lb2 = (const float*)d_in[6];
    const float* sw  = (const float*)d_in[7];
    const float* sb  = (const float*)d_in[8];
    const float* nw  = (const float*)d_in[9];
    const float* nbw = (const float*)d_in[10];
    const float* gw1 = (const float*)d_in[11];
    const float* gb1 = (const float*)d_in[12];
    const float* gw2 = (const float*)d_in[13];
    const float* gb2 = (const float*)d_in[14];
    const float* ng  = (const float*)d_in[15];
    const float* nbt = (const float*)d_in[16];
    float* out = (float*)d_out;

    float *h, *sev, *bnb, *bsg;
    cudaGetSymbolAddress((void**)&h, g_h);
    cudaGetSymbolAddress((void**)&sev, g_sev);
    cudaGetSymbolAddress((void**)&bnb, g_bnb);
    cudaGetSymbolAddress((void**)&bsg, g_bsg);
    __half *wb, *u16, *h16, *ag16;
    cudaGetSymbolAddress((void**)&wb, g_wb);
    cudaGetSymbolAddress((void**)&u16, g_u16);
    cudaGetSymbolAddress((void**)&h16, g_h16);
    cudaGetSymbolAddress((void**)&ag16, g_ag16);

    cudaFuncSetAttribute(gemm_pers<0>, cudaFuncAttributeMaxDynamicSharedMemorySize, SM_PERS);
    cudaFuncSetAttribute(gemm_pers<1>, cudaFuncAttributeMaxDynamicSharedMemorySize, SM_PERS);
    cudaFuncSetAttribute(gemm_gate, cudaFuncAttributeMaxDynamicSharedMemorySize, SM_GATE);

    // Fork/join resources (capture-legal; validated in R14/R15)
    cudaStream_t s2;
    cudaStreamCreateWithFlags(&s2, cudaStreamNonBlocking);
    cudaEvent_t evF, evJ;
    cudaEventCreateWithFlags(&evF, cudaEventDisableTiming);
    cudaEventCreateWithFlags(&evJ, cudaEventDisableTiming);

    // ---- Fork: CSR build on s2 || weight prep + lift on main ----
    cudaEventRecord(evF, 0);
    cudaStreamWaitEvent(s2, evF, 0);

    k_zero_cnt<<<SCAN_BLOCKS, 256, 0, s2>>>();
    k_count<<<(EE + 255) / 256, 256, 0, s2>>>(ei);
    k_blocksum<<<SCAN_BLOCKS, 256, 0, s2>>>();
    k_scan_bsum<<<1, 512, 0, s2>>>();
    k_rowstart<<<SCAN_BLOCKS, 256, 0, s2>>>();
    k_fill<<<(EE + 255) / 256, 256, 0, s2>>>(ei, ev);
    cudaEventRecord(evJ, s2);

    k_wcomb<<<(4 * 16384 + 255) / 256, 256>>>(nw, sw, gw1);
    k_bcomb<<<2, 256>>>(nbw, sb, gb1, gw1);
    wconv_kernel<<<(WSLOTS * 16384 + 255) / 256, 256>>>(lw2, gw2);
    lift_hidden_kernel<<<(NN * CC + 255) / 256, 256>>>(x, lw1, lb1);
    gemm_pers<0><<<PGRID, GTHREADS, SM_PERS>>>(u16, wb, lb2, nullptr, h, h16);

    cudaStreamWaitEvent(0, evJ, 0);   // join: CSR ready

    for (int l = 0; l < 2; l++) {
        const __half* wsg = wb + (size_t)(1 + 3 * l) * 16384;
        const __half* wnb = wb + (size_t)(2 + 3 * l) * 16384;
        const __half* g2  = wb + (size_t)(3 + 3 * l) * 16384;

        // gh (fp16) + sev = pull-gather of h (fp32)
        k_aggr<<<(NN + 7) / 8, 256>>>();
        // u = gelu(h@Wsg + gh@Wnb + bsg + sev*bnb)
        gemm_gate<<<PGRID, GTHREADS, SM_GATE>>>(h16, ag16, wsg, wnb,
                                                bsg + l * CC, bnb + l * CC, sev,
                                                u16);
        // h = h + u @ Wg2 + bg2  (fp32 + fp16)
        gemm_pers<1><<<PGRID, GTHREADS, SM_PERS>>>(u16, g2, gb2 + l * CC, h,
                                                   h, h16);
    }

    ln_kernel<<<(NN + 7) / 8, 256>>>(h, ng, nbt, out);
}

// round 17
// speedup vs baseline: 1.5710x; 1.0982x over previous
#include <cuda_runtime.h>
#include <cuda_fp16.h>
#include <math.h>
#include <stdint.h>

#define NN 100000
#define EE 1600000
#define CC 128
#define NTILES ((NN + 127) / 128)       // 782
#define PGRID 148
#define GTHREADS 512
#define SCAN_BLOCKS ((NN + 255) / 256)  // 391

// ---------------------------------------------------------------------------
// Scratch (allocation-free rule: __device__ globals)
// ---------------------------------------------------------------------------
__device__ float g_h[(size_t)NN * CC];     // fp32 h (resid + LN)

__device__ __half g_u16[(size_t)NN * CC];   // lift-hidden / u (fp16)
__device__ __half g_h16[(size_t)NN * CC];   // h (fp16; gather source)
__device__ __half g_ag16[(size_t)NN * CC];  // gathered h (fp16)

__device__ float g_sev[NN];                // per-row sum of edge values
__device__ float g_wnb[2 * 16384];         // Wn @ W1b (fp32)
__device__ float g_wsg[2 * 16384];         // Ws @ W1a (fp32)
__device__ float g_bnb[2 * CC];            // bn @ W1b
__device__ float g_bsg[2 * CC];            // bs @ W1a + bg1

// CSR scratch
__device__ int   g_cnt[NN];
__device__ int   g_rowstart[NN + 1];
__device__ int   g_cursor[NN];
__device__ int   g_bsum[SCAN_BLOCKS];
__device__ int   g_boff[SCAN_BLOCKS];
__device__ int   g_ecol[EE];
__device__ float g_eval[EE];

// Pre-converted fp16 weight tiles, layout [slot][n][k]
// slots: [0]=lift2; per layer l: [1+3l]=Wsg, [2+3l]=Wnb, [3+3l]=gate2.
#define WSLOTS 7
__device__ __half g_wb[(size_t)WSLOTS * 16384];

__device__ __forceinline__ float gelu_f(float v) {
    return 0.5f * v * (1.0f + erff(v * 0.7071067811865475f));
}

// ---------------------------------------------------------------------------
// mma.sync / cp.async helpers
// ---------------------------------------------------------------------------
__device__ __forceinline__ void ldsm_x4(uint32_t* r, uint32_t addr) {
    asm volatile("ldmatrix.sync.aligned.m8n8.x4.shared.b16 {%0,%1,%2,%3}, [%4];"
                 : "=r"(r[0]), "=r"(r[1]), "=r"(r[2]), "=r"(r[3]) : "r"(addr));
}
__device__ __forceinline__ void mma_f16(float* d, const uint32_t* a, const uint32_t* b) {
    asm volatile(
        "mma.sync.aligned.m16n8k16.row.col.f32.f16.f16.f32 "
        "{%0,%1,%2,%3}, {%4,%5,%6,%7}, {%8,%9}, {%0,%1,%2,%3};"
        : "+f"(d[0]), "+f"(d[1]), "+f"(d[2]), "+f"(d[3])
        : "r"(a[0]), "r"(a[1]), "r"(a[2]), "r"(a[3]), "r"(b[0]), "r"(b[1]));
}
__device__ __forceinline__ void cp16(uint32_t dst, const void* src, int srcsize) {
    asm volatile("cp.async.cg.shared.global [%0], [%1], 16, %2;"
                 :: "r"(dst), "l"(src), "r"(srcsize) : "memory");
}
__device__ __forceinline__ void cp_commit() {
    asm volatile("cp.async.commit_group;" ::: "memory");
}
__device__ __forceinline__ void cp_wait_all() {
    asm volatile("cp.async.wait_group 0;" ::: "memory");
}

// ---------------------------------------------------------------------------
// Smem layout: tiles of 128 rows x 256B (+16B pad) = 34816B.
// ---------------------------------------------------------------------------
#define ROWB 272
#define TILEB (128 * ROWB)          // 34816
#define SM_GATE (6 * TILEB)         // 208896
#define SM_PERS (3 * TILEB)         // 104448

// fp16 single-pass MMA over one staged 128-K tile; warp tile 16x64.
__device__ __forceinline__ void mma_chunk16(float acc[8][4], uint32_t aB,
                                            uint32_t bB) {
#pragma unroll
    for (int ks = 0; ks < 8; ks++) {
        uint32_t a[4], b[4][4];
        ldsm_x4(a, aB + ks * 32);
#pragma unroll
        for (int np = 0; np < 4; np++)
            ldsm_x4(b[np], bB + ks * 32 + np * 16 * ROWB);
#pragma unroll
        for (int nt = 0; nt < 8; nt++) {
            uint32_t bb[2] = { b[nt >> 1][(nt & 1) * 2], b[nt >> 1][(nt & 1) * 2 + 1] };
            mma_f16(acc[nt], a, bb);
        }
    }
}

#define ACC_ZERO16(acc)                                 \
    _Pragma("unroll")                                   \
    for (int nt = 0; nt < 8; nt++)                      \
        _Pragma("unroll")                               \
        for (int e = 0; e < 4; e++) acc[nt][e] = 0.0f;

// Stage one fp16 tile: 2048 x 16B chunks, 4 per thread (512 threads).
__device__ __forceinline__ void stage_A16(uint32_t abase, const __half* __restrict__ A,
                                          int m0, int tid) {
#pragma unroll
    for (int i = 0; i < 4; i++) {
        int ci = tid + i * GTHREADS;
        int row = ci >> 4, ch = ci & 15;
        int gm = m0 + row;
        int ss = (gm < NN) ? 16 : 0;
        int gms = (gm < NN) ? gm : (NN - 1);
        cp16(abase + (uint32_t)(row * ROWB + ch * 16),
             A + (size_t)gms * 128 + ch * 8, ss);
    }
}
__device__ __forceinline__ void stage_B16(uint32_t bbase, const __half* __restrict__ B,
                                          int tid) {
#pragma unroll
    for (int i = 0; i < 4; i++) {
        int ci = tid + i * GTHREADS;
        int row = ci >> 4, ch = ci & 15;
        cp16(bbase + (uint32_t)(row * ROWB + ch * 16), B + ci * 8, 16);
    }
}

// ---------------------------------------------------------------------------
// Persistent GEMM, 512 threads. RESID: 0 none, 1 post-act.
// Writes fp32 (+resid) and fp16 copies.
// ---------------------------------------------------------------------------
template <int RESID>
__global__ void __launch_bounds__(GTHREADS, 1) gemm_pers(
    const __half* __restrict__ A16, const __half* __restrict__ B16,
    const float* __restrict__ bias, const float* __restrict__ R,
    float* __restrict__ OutF, __half* __restrict__ Out16) {
    extern __shared__ __align__(16) char smem[];
    const uint32_t sb = (uint32_t)__cvta_generic_to_shared(smem);
    const int tid = threadIdx.x;
    const int lane = tid & 31;
    const int warp_m = (tid >> 5) >> 1;   // 0..7, 16 rows
    const int warp_n = (tid >> 5) & 1;    // 0..1, 64 cols

    const uint32_t a_lane = (uint32_t)((lane & 15) * ROWB + (lane >> 4) * 16) +
                            (uint32_t)(warp_m * 16 * ROWB);
    const uint32_t b_lane = (uint32_t)(((lane & 7) + ((lane >> 4) & 1) * 8) * ROWB +
                                       ((lane >> 3) & 1) * 16) +
                            (uint32_t)(warp_n * 64 * ROWB);
    const uint32_t bB = sb + b_lane;            // B in slot 0

    float b0[8], b1[8];
#pragma unroll
    for (int nt = 0; nt < 8; nt++) {
        int col = warp_n * 64 + nt * 8 + (lane & 3) * 2;
        b0[nt] = __ldg(bias + col);
        b1[nt] = __ldg(bias + col + 1);
    }

    stage_B16(sb, B16, tid);
    int tile = blockIdx.x;
    if (tile < NTILES) stage_A16(sb + TILEB, A16, tile * 128, tid);
    cp_commit();
    cp_wait_all();
    __syncthreads();

    int buf = 0;
    for (; tile < NTILES; tile += PGRID) {
        const int m0 = tile * 128;
        const int nxt = tile + PGRID;
        if (nxt < NTILES)
            stage_A16(sb + (buf ? TILEB : 2 * TILEB), A16, nxt * 128, tid);
        cp_commit();

        float acc[8][4];
        ACC_ZERO16(acc);
        mma_chunk16(acc, sb + (buf ? 2 * TILEB : TILEB) + a_lane, bB);

        int r0 = m0 + warp_m * 16 + (lane >> 2);
#pragma unroll
        for (int half = 0; half < 2; half++) {
            int r = r0 + half * 8;
            if (r >= NN) continue;
            const float* rrow = RESID ? (R + (size_t)r * 128) : nullptr;
#pragma unroll
            for (int nt = 0; nt < 8; nt++) {
                int col = warp_n * 64 + nt * 8 + (lane & 3) * 2;
                float x0 = acc[nt][half * 2 + 0] + b0[nt];
                float x1 = acc[nt][half * 2 + 1] + b1[nt];
                if (RESID) {
                    float2 rr = *(const float2*)(rrow + col);
                    x0 += rr.x; x1 += rr.y;
                }
                *(float2*)(OutF + (size_t)r * 128 + col) = make_float2(x0, x1);
                *(__half2*)(Out16 + (size_t)r * 128 + col) =
                    __floats2half2_rn(x0, x1);
            }
        }
        cp_wait_all();
        __syncthreads();
        buf ^= 1;
    }
}

// ---------------------------------------------------------------------------
// Persistent fused gate kernel, 512 threads, fully double-buffered:
//   u = gelu(h@Wsg + gh@Wnb + bsg + sev*bnb)
// Slots: 0=Wsg, 1=Wnb, 2=h0, 3=gh0, 4=h1, 5=gh1.
// ---------------------------------------------------------------------------
__global__ void __launch_bounds__(GTHREADS, 1) gemm_gate(
    const __half* __restrict__ H16, const __half* __restrict__ G16,
    const __half* __restrict__ Wsg, const __half* __restrict__ Wnb,
    const float* __restrict__ bsg, const float* __restrict__ bnb,
    const float* __restrict__ sev, __half* __restrict__ Out16) {
    extern __shared__ __align__(16) char smem[];
    const uint32_t sb = (uint32_t)__cvta_generic_to_shared(smem);
    const int tid = threadIdx.x;
    const int lane = tid & 31;
    const int warp_m = (tid >> 5) >> 1;
    const int warp_n = (tid >> 5) & 1;

    const uint32_t a_lane = (uint32_t)((lane & 15) * ROWB + (lane >> 4) * 16) +
                            (uint32_t)(warp_m * 16 * ROWB);
    const uint32_t b_lane = (uint32_t)(((lane & 7) + ((lane >> 4) & 1) * 8) * ROWB +
                                       ((lane >> 3) & 1) * 16) +
                            (uint32_t)(warp_n * 64 * ROWB);
    const uint32_t bSG = sb + b_lane;
    const uint32_t bNB = sb + TILEB + b_lane;

    float b0[8], b1[8], cv0[8], cv1[8];
#pragma unroll
    for (int nt = 0; nt < 8; nt++) {
        int col = warp_n * 64 + nt * 8 + (lane & 3) * 2;
        b0[nt] = __ldg(bsg + col);
        b1[nt] = __ldg(bsg + col + 1);
        cv0[nt] = __ldg(bnb + col);
        cv1[nt] = __ldg(bnb + col + 1);
    }

    stage_B16(sb, Wsg, tid);
    stage_B16(sb + TILEB, Wnb, tid);
    int tile = blockIdx.x;
    if (tile < NTILES) {
        stage_A16(sb + 2 * TILEB, H16, tile * 128, tid);
        stage_A16(sb + 3 * TILEB, G16, tile * 128, tid);
    }
    cp_commit();
    cp_wait_all();
    __syncthreads();

    int buf = 0;
    for (; tile < NTILES; tile += PGRID) {
        const int m0 = tile * 128;
        const int nxt = tile + PGRID;
        if (nxt < NTILES) {
            stage_A16(sb + (buf ? 2 : 4) * TILEB, H16, nxt * 128, tid);
            stage_A16(sb + (buf ? 3 : 5) * TILEB, G16, nxt * 128, tid);
        }
        cp_commit();

        float acc[8][4];
        ACC_ZERO16(acc);
        const uint32_t aH = sb + (buf ? 4 : 2) * TILEB + a_lane;
        const uint32_t aG = sb + (buf ? 5 : 3) * TILEB + a_lane;
        mma_chunk16(acc, aH, bSG);
        mma_chunk16(acc, aG, bNB);

        int r0 = m0 + warp_m * 16 + (lane >> 2);
#pragma unroll
        for (int half = 0; half < 2; half++) {
            int r = r0 + half * 8;
            if (r >= NN) continue;
            float sv = __ldg(sev + r);
#pragma unroll
            for (int nt = 0; nt < 8; nt++) {
                int col = warp_n * 64 + nt * 8 + (lane & 3) * 2;
                float x0 = gelu_f(fmaf(sv, cv0[nt], acc[nt][half * 2 + 0] + b0[nt]));
                float x1 = gelu_f(fmaf(sv, cv1[nt], acc[nt][half * 2 + 1] + b1[nt]));
                *(__half2*)(Out16 + (size_t)r * 128 + col) =
                    __floats2half2_rn(x0, x1);
            }
        }
        cp_wait_all();
        __syncthreads();
        buf ^= 1;
    }
}

// ---------------------------------------------------------------------------
// Combined weights (fp32, exact)
// ---------------------------------------------------------------------------
__global__ void k_wcomb(const float* __restrict__ nw, const float* __restrict__ sw,
                        const float* __restrict__ gw1) {
    int idx = blockIdx.x * blockDim.x + threadIdx.x;
    if (idx >= 4 * 16384) return;
    int which = idx >> 15;            // 0 = Wnb, 1 = Wsg
    int sub = idx & 32767;
    int l = sub >> 14;
    int k = (sub >> 7) & 127;
    int n = sub & 127;
    const float* a;
    const float* b;
    if (which == 0) {
        a = nw + (size_t)l * 16384 + k * 128;
        b = gw1 + (size_t)l * 32768 + 16384 + n;
    } else {
        a = sw + (size_t)l * 16384 + k * 128;
        b = gw1 + (size_t)l * 32768 + n;
    }
    float s = 0.0f;
#pragma unroll 8
    for (int m = 0; m < 128; m++) s = fmaf(a[m], b[(size_t)m * 128], s);
    if (which == 0) g_wnb[sub] = s;
    else            g_wsg[sub] = s;
}
__global__ void k_bcomb(const float* __restrict__ nbw, const float* __restrict__ sb,
                        const float* __restrict__ gb1, const float* __restrict__ gw1) {
    int idx = blockIdx.x * blockDim.x + threadIdx.x;
    if (idx >= 4 * CC) return;
    int which = idx >> 8;             // 0 = bnb, 1 = bsg
    int l = (idx >> 7) & 1, n = idx & 127;
    float s = 0.0f;
    if (which == 0) {
#pragma unroll 8
        for (int m = 0; m < 128; m++)
            s = fmaf(nbw[l * 128 + m],
                     gw1[(size_t)l * 32768 + 16384 + (size_t)m * 128 + n], s);
        g_bnb[l * CC + n] = s;
    } else {
#pragma unroll 8
        for (int m = 0; m < 128; m++)
            s = fmaf(sb[l * 128 + m], gw1[(size_t)l * 32768 + (size_t)m * 128 + n], s);
        g_bsg[l * CC + n] = s + gb1[l * 128 + n];
    }
}

// ---------------------------------------------------------------------------
// Weight conversion: fp32 W[K,N] -> fp16 B[N,K]
// ---------------------------------------------------------------------------
__global__ void wconv_kernel(const float* __restrict__ lw2,
                             const float* __restrict__ gw2) {
    int idx = blockIdx.x * blockDim.x + threadIdx.x;
    if (idx >= WSLOTS * 16384) return;
    int slot = idx >> 14;
    int within = idx & 16383;
    int n = within >> 7;
    int k = within & 127;
    const float* src;
    if (slot == 0) {
        src = lw2 + k * 128 + n;
    } else {
        int l = (slot - 1) / 3, j = (slot - 1) % 3;
        if (j == 0)      src = g_wsg + (size_t)l * 16384 + k * 128 + n;
        else if (j == 1) src = g_wnb + (size_t)l * 16384 + k * 128 + n;
        else             src = gw2 + (size_t)l * 16384 + k * 128 + n;
    }
    g_wb[idx] = __float2half_rn(*src);
}

// ---------------------------------------------------------------------------
// CSR build
// ---------------------------------------------------------------------------
__global__ void k_zero_cnt() {
    int i = blockIdx.x * blockDim.x + threadIdx.x;
    if (i < NN) g_cnt[i] = 0;
}
__global__ void k_count(const int* __restrict__ ei) {
    int e = blockIdx.x * blockDim.x + threadIdx.x;
    if (e < EE) atomicAdd(&g_cnt[ei[e]], 1);
}
__global__ void k_blocksum() {
    __shared__ int sh[256];
    int i = blockIdx.x * 256 + threadIdx.x;
    int v = (i < NN) ? g_cnt[i] : 0;
    sh[threadIdx.x] = v;
    __syncthreads();
    for (int s = 128; s; s >>= 1) {
        if (threadIdx.x < s) sh[threadIdx.x] += sh[threadIdx.x + s];
        __syncthreads();
    }
    if (threadIdx.x == 0) g_bsum[blockIdx.x] = sh[0];
}
__global__ void k_scan_bsum() {
    __shared__ int sh[512];
    int t = threadIdx.x;
    sh[t] = (t < SCAN_BLOCKS) ? g_bsum[t] : 0;
    __syncthreads();
    for (int off = 1; off < 512; off <<= 1) {
        int v = (t >= off) ? sh[t - off] : 0;
        __syncthreads();
        sh[t] += v;
        __syncthreads();
    }
    if (t < SCAN_BLOCKS) g_boff[t] = sh[t] - g_bsum[t];
}
__global__ void k_rowstart() {
    __shared__ int sh[256];
    int i = blockIdx.x * 256 + threadIdx.x;
    int v = (i < NN) ? g_cnt[i] : 0;
    sh[threadIdx.x] = v;
    __syncthreads();
    for (int off = 1; off < 256; off <<= 1) {
        int u = (threadIdx.x >= off) ? sh[threadIdx.x - off] : 0;
        __syncthreads();
        sh[threadIdx.x] += u;
        __syncthreads();
    }
    if (i < NN) {
        int excl = sh[threadIdx.x] - v + g_boff[blockIdx.x];
        g_rowstart[i] = excl;
        g_cursor[i] = excl;
        if (i == NN - 1) g_rowstart[NN] = excl + v;
    }
}
__global__ void k_fill(const int* __restrict__ ei, const float* __restrict__ ev) {
    int e = blockIdx.x * blockDim.x + threadIdx.x;
    if (e >= EE) return;
    int row = ei[e];
    int pos = atomicAdd(&g_cursor[row], 1);
    g_ecol[pos] = ei[EE + e];
    g_eval[pos] = ev[e];
}

// ---------------------------------------------------------------------------
// Pull aggregation from fp16 h: gh[r] = sum ev*h16[col]; sev[r] = sum ev.
// Lane covers cols {2L,2L+1,64+2L,65+2L} via half2 loads (2 LDG.32/edge).
// ---------------------------------------------------------------------------
__global__ void k_aggr() {
    int r = blockIdx.x * 8 + (threadIdx.x >> 5);
    if (r >= NN) return;
    int lane = threadIdx.x & 31;
    int s = g_rowstart[r];
    int e = g_rowstart[r + 1];
    float acc[4] = {0.f, 0.f, 0.f, 0.f};
    float sev = 0.f;
    const __half2* hbase = (const __half2*)g_h16;
    for (int j = s; j < e; j++) {
        int c = __ldg(&g_ecol[j]);
        float v = __ldg(&g_eval[j]);
        sev += v;
        const __half2* srow = hbase + (size_t)c * 64;
        float2 p0 = __half22float2(__ldg(srow + lane));
        float2 p1 = __half22float2(__ldg(srow + lane + 32));
        acc[0] = fmaf(p0.x, v, acc[0]);
        acc[1] = fmaf(p0.y, v, acc[1]);
        acc[2] = fmaf(p1.x, v, acc[2]);
        acc[3] = fmaf(p1.y, v, acc[3]);
    }
    __half2* d = (__half2*)g_ag16 + (size_t)r * 64;
    d[lane]      = __floats2half2_rn(acc[0], acc[1]);
    d[lane + 32] = __floats2half2_rn(acc[2], acc[3]);
    if (lane == 0) g_sev[r] = sev;
}

// ---------------------------------------------------------------------------
// Lift stage 1 + LayerNorm
// ---------------------------------------------------------------------------
__global__ void lift_hidden_kernel(const float* __restrict__ x,
                                   const float* __restrict__ w1,
                                   const float* __restrict__ b1) {
    int idx = blockIdx.x * blockDim.x + threadIdx.x;
    if (idx >= NN * CC) return;
    int n = idx >> 7;
    int c = idx & 127;
    const float* xr = x + (size_t)n * 9 + 3;
    float acc = b1[c];
#pragma unroll
    for (int i = 0; i < 6; i++)
        acc = fmaf(xr[i], w1[i * CC + c], acc);
    g_u16[idx] = __float2half_rn(gelu_f(acc));
}

__global__ void ln_kernel(const float* __restrict__ h,
                          const float* __restrict__ g,
                          const float* __restrict__ b,
                          float* __restrict__ out) {
    int n = blockIdx.x * 8 + (threadIdx.x >> 5);
    if (n >= NN) return;
    int lane = threadIdx.x & 31;
    const float* r = h + (size_t)n * CC;
    float v[4];
    float s = 0.f;
#pragma unroll
    for (int i = 0; i < 4; i++) { v[i] = r[lane + i * 32]; s += v[i]; }
#pragma unroll
    for (int o = 16; o; o >>= 1) s += __shfl_xor_sync(0xffffffffu, s, o);
    float mu = s * (1.f / 128.f);
    float q = 0.f;
#pragma unroll
    for (int i = 0; i < 4; i++) { float d = v[i] - mu; q = fmaf(d, d, q); }
#pragma unroll
    for (int o = 16; o; o >>= 1) q += __shfl_xor_sync(0xffffffffu, q, o);
    float inv = rsqrtf(q * (1.f / 128.f) + 1e-5f);
#pragma unroll
    for (int i = 0; i < 4; i++) {
        int c = lane + i * 32;
        out[(size_t)n * CC + c] = fmaf((v[i] - mu) * inv, g[c], b[c]);
    }
}

// ---------------------------------------------------------------------------
extern "C" void kernel_launch(void* const* d_in, const int* in_sizes, int n_in,
                              void* d_out, int out_size) {
    const float* x   = (const float*)d_in[0];
    const int*   ei  = (const int*)d_in[1];
    const float* ev  = (const float*)d_in[2];
    const float* lw1 = (const float*)d_in[3];
    const float* lb1 = (const float*)d_in[4];
    const float* lw2 = (const float*)d_in[5];
    const float* lb2 = (const float*)d_in[6];
    const float* sw  = (const float*)d_in[7];
    const float* sb  = (const float*)d_in[8];
    const float* nw  = (const float*)d_in[9];
    const float* nbw = (const float*)d_in[10];
    const float* gw1 = (const float*)d_in[11];
    const float* gb1 = (const float*)d_in[12];
    const float* gw2 = (const float*)d_in[13];
    const float* gb2 = (const float*)d_in[14];
    const float* ng  = (const float*)d_in[15];
    const float* nbt = (const float*)d_in[16];
    float* out = (float*)d_out;

    float *h, *sev, *bnb, *bsg;
    cudaGetSymbolAddress((void**)&h, g_h);
    cudaGetSymbolAddress((void**)&sev, g_sev);
    cudaGetSymbolAddress((void**)&bnb, g_bnb);
    cudaGetSymbolAddress((void**)&bsg, g_bsg);
    __half *wb, *u16, *h16, *ag16;
    cudaGetSymbolAddress((void**)&wb, g_wb);
    cudaGetSymbolAddress((void**)&u16, g_u16);
    cudaGetSymbolAddress((void**)&h16, g_h16);
    cudaGetSymbolAddress((void**)&ag16, g_ag16);

    cudaFuncSetAttribute(gemm_pers<0>, cudaFuncAttributeMaxDynamicSharedMemorySize, SM_PERS);
    cudaFuncSetAttribute(gemm_pers<1>, cudaFuncAttributeMaxDynamicSharedMemorySize, SM_PERS);
    cudaFuncSetAttribute(gemm_gate, cudaFuncAttributeMaxDynamicSharedMemorySize, SM_GATE);

    // Fork/join resources (capture-legal; validated R14/R15)
    cudaStream_t s2;
    cudaStreamCreateWithFlags(&s2, cudaStreamNonBlocking);
    cudaEvent_t evF, evJ;
    cudaEventCreateWithFlags(&evF, cudaEventDisableTiming);
    cudaEventCreateWithFlags(&evJ, cudaEventDisableTiming);

    // ---- Fork: CSR build on s2 || weight prep + lift on main ----
    cudaEventRecord(evF, 0);
    cudaStreamWaitEvent(s2, evF, 0);

    k_zero_cnt<<<SCAN_BLOCKS, 256, 0, s2>>>();
    k_count<<<(EE + 255) / 256, 256, 0, s2>>>(ei);
    k_blocksum<<<SCAN_BLOCKS, 256, 0, s2>>>();
    k_scan_bsum<<<1, 512, 0, s2>>>();
    k_rowstart<<<SCAN_BLOCKS, 256, 0, s2>>>();
    k_fill<<<(EE + 255) / 256, 256, 0, s2>>>(ei, ev);
    cudaEventRecord(evJ, s2);

    k_wcomb<<<(4 * 16384 + 255) / 256, 256>>>(nw, sw, gw1);
    k_bcomb<<<2, 256>>>(nbw, sb, gb1, gw1);
    wconv_kernel<<<(WSLOTS * 16384 + 255) / 256, 256>>>(lw2, gw2);
    lift_hidden_kernel<<<(NN * CC + 255) / 256, 256>>>(x, lw1, lb1);
    gemm_pers<0><<<PGRID, GTHREADS, SM_PERS>>>(u16, wb, lb2, nullptr, h, h16);

    cudaStreamWaitEvent(0, evJ, 0);   // join: CSR ready

    for (int l = 0; l < 2; l++) {
        const __half* wsg = wb + (size_t)(1 + 3 * l) * 16384;
        const __half* wnb = wb + (size_t)(2 + 3 * l) * 16384;
        const __half* g2  = wb + (size_t)(3 + 3 * l) * 16384;

        // gh (fp16) + sev = pull-gather of h16
        k_aggr<<<(NN + 7) / 8, 256>>>();
        // u = gelu(h@Wsg + gh@Wnb + bsg + sev*bnb)
        gemm_gate<<<PGRID, GTHREADS, SM_GATE>>>(h16, ag16, wsg, wnb,
                                                bsg + l * CC, bnb + l * CC, sev,
                                                u16);
        // h = h + u @ Wg2 + bg2  (fp32 + fp16)
        gemm_pers<1><<<PGRID, GTHREADS, SM_PERS>>>(u16, g2, gb2 + l * CC, h,
                                                   h, h16);
    }

    ln_kernel<<<(NN + 7) / 8, 256>>>(h, ng, nbt, out);
}